// round 2
// baseline (speedup 1.0000x reference)
#include <cuda_runtime.h>
#include <math.h>

#define NMAX 100000
#define EMAX 800000
#define ENMAX (NMAX + EMAX)

// ------------------------- static scratch (no allocs allowed) ----------------
__device__ float g_X0L[NMAX * 128];
__device__ float g_X0R[NMAX * 128];
__device__ float g_XSL[3 * NMAX * 128];
__device__ float g_XSR[3 * NMAX * 128];
__device__ float g_MEAN[NMAX * 128];
__device__ float g_XH[NMAX * 256];
__device__ float g_ASRC[NMAX * 2];
__device__ float g_ADST[NMAX * 2];
__device__ float g_GI[3 * NMAX * 768];
__device__ float g_GB[NMAX * 768];
__device__ float g_H[NMAX * 192];
__device__ float g_C[NMAX * 192];
__device__ float g_SCF[3 * NMAX];
__device__ float g_SCB[3 * NMAX];
__device__ float g_JKL[NMAX * 128];
__device__ float g_JKR[NMAX * 128];
__device__ float g_SQL[NMAX * 128];
__device__ float g_SQR[NMAX * 128];
__device__ float g_OUTS[4 * NMAX * 128];
__device__ float g_WIHT[4 * 128 * 768];
__device__ float g_WHHT[4 * 192 * 768];
__device__ float g_BSUM[4 * 768];
__device__ int   g_deg[NMAX];          // also reused as fill cursor
__device__ int   g_indptrL[NMAX + 1];
__device__ int   g_indptrR[NMAX + 1];
__device__ int   g_csrL[ENMAX];
__device__ int   g_csrR[ENMAX];

// ------------------------------ helpers --------------------------------------
__device__ __forceinline__ float wredsum(float v) {
#pragma unroll
    for (int o = 16; o; o >>= 1) v += __shfl_xor_sync(0xffffffffu, v, o);
    return v;
}
__device__ __forceinline__ float wredmax(float v) {
#pragma unroll
    for (int o = 16; o; o >>= 1) v = fmaxf(v, __shfl_xor_sync(0xffffffffu, v, o));
    return v;
}
__device__ __forceinline__ float sigf(float x) { return 1.0f / (1.0f + expf(-x)); }

// ------------------------------ CSR build ------------------------------------
__global__ void k_deg_init(int* deg, int n) {
    int i = blockIdx.x * blockDim.x + threadIdx.x;
    if (i < n) deg[i] = 1;  // self loop
}
__global__ void k_deg_count(int* deg, const int* dst, int e) {
    int i = blockIdx.x * blockDim.x + threadIdx.x;
    if (i < e) atomicAdd(&deg[dst[i]], 1);
}
__global__ void k_scan_excl(const int* __restrict__ in, int* __restrict__ out, int n) {
    __shared__ int sh[1024];
    __shared__ int carry;
    if (threadIdx.x == 0) carry = 0;
    __syncthreads();
    for (int base = 0; base < n; base += 1024) {
        int i = base + threadIdx.x;
        int v = (i < n) ? in[i] : 0;
        sh[threadIdx.x] = v;
        __syncthreads();
        for (int off = 1; off < 1024; off <<= 1) {
            int t = (threadIdx.x >= off) ? sh[threadIdx.x - off] : 0;
            __syncthreads();
            sh[threadIdx.x] += t;
            __syncthreads();
        }
        if (i < n) out[i] = carry + sh[threadIdx.x] - v;
        int tot = sh[1023];
        __syncthreads();
        if (threadIdx.x == 0) carry += tot;
        __syncthreads();
    }
    if (threadIdx.x == 0) out[n] = carry;
}
__global__ void k_fill_self(const int* indptr, int* csr, int* pos, int n) {
    int i = blockIdx.x * blockDim.x + threadIdx.x;
    if (i < n) {
        int p = indptr[i];
        csr[p] = i;
        pos[i] = p + 1;
    }
}
__global__ void k_fill_edges(const int* src, const int* dst, int* pos, int* csr, int e) {
    int i = blockIdx.x * blockDim.x + threadIdx.x;
    if (i < e) {
        int p = atomicAdd(&pos[dst[i]], 1);
        csr[p] = src[i];
    }
}

// ------------------------------ features -------------------------------------
__global__ void k_init_x(const int* __restrict__ x_idx, const float* __restrict__ x_flt,
                         const float* __restrict__ eaa, const float* __restrict__ ess,
                         float* __restrict__ XL, float* __restrict__ XR, int n) {
    int idx = blockIdx.x * blockDim.x + threadIdx.x;
    if (idx >= n * 128) return;
    int node = idx >> 7, c = idx & 127;
    float vl, vr;
    if (c < 123) {
        int i0 = x_idx[node * 2], i1 = x_idx[node * 2 + 1];
        vl = eaa[i0 * 123 + c] + ess[i1 * 123 + c];
        vr = eaa[26 * 123 + i0 * 123 + c] + ess[3 * 123 + i1 * 123 + c];
    } else {
        float f = x_flt[node * 5 + (c - 123)];
        vl = f; vr = f;
    }
    XL[idx] = vl;
    XR[idx] = vr;
}
__global__ void k_mean(const float* __restrict__ A, const float* __restrict__ B,
                       float* __restrict__ M, int total) {
    int i = blockIdx.x * blockDim.x + threadIdx.x;
    if (i < total) M[i] = 0.5f * (A[i] + B[i]);
}
__global__ void k_zero(float* p, int total) {
    int i = blockIdx.x * blockDim.x + threadIdx.x;
    if (i < total) p[i] = 0.0f;
}

// ------------------------------ GEMM (fp32, 128x128 tile, 8x8 micro) ---------
// C[M,N] = A[M,K] @ B[K,N]  (+ D if flags&1) (+ bias[N] if flags&2)
// Requires N % 128 == 0, K % 16 == 0.
__global__ void __launch_bounds__(256)
gemm128(const float* __restrict__ A, const float* __restrict__ B,
        const float* __restrict__ D, const float* __restrict__ bias,
        float* __restrict__ C, int M, int N, int K, int flags) {
    __shared__ float As[16][128];
    __shared__ float Bs[16][128];
    const int tid = threadIdx.x;
    const int tx = tid & 15, ty = tid >> 4;
    const int bm = blockIdx.y * 128, bn = blockIdx.x * 128;
    float acc[8][8];
#pragma unroll
    for (int i = 0; i < 8; i++)
#pragma unroll
        for (int j = 0; j < 8; j++) acc[i][j] = 0.0f;

    for (int k0 = 0; k0 < K; k0 += 16) {
#pragma unroll
        for (int i = 0; i < 8; i++) {
            int idx = tid + i * 256;
            int k = idx & 15, r = idx >> 4;
            int gr = bm + r;
            As[k][r] = (gr < M) ? A[(size_t)gr * K + (k0 + k)] : 0.0f;
        }
#pragma unroll
        for (int i = 0; i < 8; i++) {
            int idx = tid + i * 256;
            int c = idx & 127, k = idx >> 7;
            Bs[k][c] = B[(size_t)(k0 + k) * N + (bn + c)];
        }
        __syncthreads();
#pragma unroll
        for (int kk = 0; kk < 16; kk++) {
            float a[8], b[8];
            *(float4*)&a[0] = *(const float4*)&As[kk][ty * 8];
            *(float4*)&a[4] = *(const float4*)&As[kk][ty * 8 + 4];
            *(float4*)&b[0] = *(const float4*)&Bs[kk][tx * 8];
            *(float4*)&b[4] = *(const float4*)&Bs[kk][tx * 8 + 4];
#pragma unroll
            for (int i = 0; i < 8; i++)
#pragma unroll
                for (int j = 0; j < 8; j++) acc[i][j] = fmaf(a[i], b[j], acc[i][j]);
        }
        __syncthreads();
    }
#pragma unroll
    for (int i = 0; i < 8; i++) {
        int r = bm + ty * 8 + i;
        if (r >= M) continue;
#pragma unroll
        for (int j = 0; j < 8; j++) {
            int c = bn + tx * 8 + j;
            float v = acc[i][j];
            if (flags & 2) v += bias[c];
            if (flags & 1) v += D[(size_t)r * N + c];
            C[(size_t)r * N + c] = v;
        }
    }
}

// ------------------------------ GAT ------------------------------------------
// per-node attention logits: a_src[n,h] = <xh[n,h,:], att_src[h,:]>, same for dst
__global__ void k_att(const float* __restrict__ XH, const float* __restrict__ ws,
                      const float* __restrict__ wd, float* __restrict__ asrc,
                      float* __restrict__ adst, int n) {
    int warp = (blockIdx.x * blockDim.x + threadIdx.x) >> 5;
    int lane = threadIdx.x & 31;
    if (warp >= n) return;
    const float* row = XH + (size_t)warp * 256;
    float s0 = 0, s1 = 0, d0 = 0, d1 = 0;
#pragma unroll
    for (int k = 0; k < 4; k++) {
        int c = lane + 32 * k;
        float x0 = row[c], x1 = row[128 + c];
        s0 += x0 * ws[c];  s1 += x1 * ws[128 + c];
        d0 += x0 * wd[c];  d1 += x1 * wd[128 + c];
    }
    s0 = wredsum(s0); s1 = wredsum(s1); d0 = wredsum(d0); d1 = wredsum(d1);
    if (lane == 0) {
        asrc[warp * 2] = s0; asrc[warp * 2 + 1] = s1;
        adst[warp * 2] = d0; adst[warp * 2 + 1] = d1;
    }
}

// warp per destination node: segment softmax + weighted aggregation over CSR
__global__ void k_gat_agg(const float* __restrict__ XH, const int* __restrict__ indptr,
                          const int* __restrict__ csr, const float* __restrict__ asrc,
                          const float* __restrict__ adst, const float* __restrict__ mean,
                          const float* __restrict__ bias, float* __restrict__ Xout, int n) {
    int warp = (blockIdx.x * blockDim.x + threadIdx.x) >> 5;
    int lane = threadIdx.x & 31;
    if (warp >= n) return;
    int beg = indptr[warp], end = indptr[warp + 1];
    float ad0 = adst[warp * 2], ad1 = adst[warp * 2 + 1];

    float m0 = -1e30f, m1 = -1e30f;
    for (int j = beg + lane; j < end; j += 32) {
        int s = csr[j];
        float e0 = asrc[s * 2] + ad0;     e0 = (e0 > 0.f) ? e0 : 0.2f * e0;
        float e1 = asrc[s * 2 + 1] + ad1; e1 = (e1 > 0.f) ? e1 : 0.2f * e1;
        m0 = fmaxf(m0, e0); m1 = fmaxf(m1, e1);
    }
    m0 = wredmax(m0); m1 = wredmax(m1);

    float d0 = 0.f, d1 = 0.f;
    for (int j = beg + lane; j < end; j += 32) {
        int s = csr[j];
        float e0 = asrc[s * 2] + ad0;     e0 = (e0 > 0.f) ? e0 : 0.2f * e0;
        float e1 = asrc[s * 2 + 1] + ad1; e1 = (e1 > 0.f) ? e1 : 0.2f * e1;
        d0 += expf(e0 - m0); d1 += expf(e1 - m1);
    }
    d0 = wredsum(d0); d1 = wredsum(d1);
    float inv0 = 1.0f / (d0 + 1e-16f), inv1 = 1.0f / (d1 + 1e-16f);

    float acc[8];
#pragma unroll
    for (int k = 0; k < 8; k++) acc[k] = 0.f;
    for (int j = beg; j < end; j++) {
        int s = csr[j];
        float e0 = asrc[s * 2] + ad0;     e0 = (e0 > 0.f) ? e0 : 0.2f * e0;
        float e1 = asrc[s * 2 + 1] + ad1; e1 = (e1 > 0.f) ? e1 : 0.2f * e1;
        float w0 = expf(e0 - m0) * inv0;
        float w1 = expf(e1 - m1) * inv1;
        const float* row = XH + (size_t)s * 256;
#pragma unroll
        for (int k = 0; k < 4; k++) {
            int c = lane + 32 * k;
            acc[k]     += row[c] * w0;
            acc[k + 4] += row[128 + c] * w1;
        }
    }
#pragma unroll
    for (int k = 0; k < 4; k++) {
        int c = lane + 32 * k;
        float v = 0.5f * (acc[k] + acc[k + 4]) + bias[c];
        v = (v > 0.f) ? v : 0.f;
        Xout[(size_t)warp * 128 + c] = mean[(size_t)warp * 128 + c] + v;
    }
}

// ------------------------------ LSTM / JK ------------------------------------
__global__ void k_bsum(const float* bih, const float* bhh, float* bsum, int total) {
    int i = blockIdx.x * blockDim.x + threadIdx.x;
    if (i < total) bsum[i] = bih[i] + bhh[i];
}
// W: [mats][768][C] -> WT: [mats][C][768]
__global__ void k_transpose_w(const float* __restrict__ W, float* __restrict__ WT,
                              int C, int total) {
    int idx = blockIdx.x * blockDim.x + threadIdx.x;
    if (idx >= total) return;
    int per = 768 * C;
    int m = idx / per, rem = idx % per;
    int r = rem / C, c = rem % C;
    WT[(size_t)m * per + (size_t)c * 768 + r] = W[idx];
}
__global__ void k_lstm_cell(const float* __restrict__ G, float* __restrict__ H,
                            float* __restrict__ Cc, int n) {
    int idx = blockIdx.x * blockDim.x + threadIdx.x;
    if (idx >= n * 192) return;
    int node = idx / 192, u = idx - node * 192;
    const float* g = G + (size_t)node * 768;
    float gi = g[u], gf = g[192 + u], gg = g[384 + u], go = g[576 + u];
    float c = Cc[idx];
    c = sigf(gf) * c + sigf(gi) * tanhf(gg);
    H[idx] = sigf(go) * tanhf(c);
    Cc[idx] = c;
}
__global__ void k_lstm_score(const float* __restrict__ H, const float* __restrict__ w,
                             float* __restrict__ sc, int n) {
    int warp = (blockIdx.x * blockDim.x + threadIdx.x) >> 5;
    int lane = threadIdx.x & 31;
    if (warp >= n) return;
    float p = 0.f;
#pragma unroll
    for (int k = 0; k < 6; k++) {
        int u = lane + 32 * k;
        p += H[(size_t)warp * 192 + u] * w[u];
    }
    p = wredsum(p);
    if (lane == 0) sc[warp] = p;
}
__global__ void k_jk(const float* __restrict__ XS, const float* __restrict__ SCF,
                     const float* __restrict__ SCB, float* __restrict__ JK, int n) {
    int idx = blockIdx.x * blockDim.x + threadIdx.x;
    if (idx >= n * 128) return;
    int node = idx >> 7;
    float s0 = SCF[node] + SCB[node];
    float s1 = SCF[n + node] + SCB[n + node];
    float s2 = SCF[2 * n + node] + SCB[2 * n + node];
    float m = fmaxf(s0, fmaxf(s1, s2));
    float e0 = expf(s0 - m), e1 = expf(s1 - m), e2 = expf(s2 - m);
    float inv = 1.0f / (e0 + e1 + e2);
    float v = e0 * XS[idx] + e1 * XS[(size_t)n * 128 + idx] + e2 * XS[(size_t)2 * n * 128 + idx];
    JK[idx] = v * inv;
}

// ------------------------------ final ----------------------------------------
__global__ void k_final(const float* __restrict__ OUTS, const float* __restrict__ lw,
                        float* __restrict__ out, int n) {
    int warp = (blockIdx.x * blockDim.x + threadIdx.x) >> 5;
    int lane = threadIdx.x & 31;
    if (warp >= n) return;
    float v[4][4];
    float s[4];
#pragma unroll
    for (int i = 0; i < 4; i++) {
        const float* row = OUTS + (size_t)i * n * 128 + (size_t)warp * 128;
        float p = 0.f;
#pragma unroll
        for (int k = 0; k < 4; k++) {
            int c = lane + 32 * k;
            v[i][k] = row[c];
            p += v[i][k] * lw[c];
        }
        s[i] = wredsum(p);
    }
    float m = fmaxf(fmaxf(s[0], s[1]), fmaxf(s[2], s[3]));
    float e[4];
    float den = 0.f;
#pragma unroll
    for (int i = 0; i < 4; i++) { e[i] = expf(s[i] - m); den += e[i]; }
    float inv = 1.0f / den;
#pragma unroll
    for (int k = 0; k < 4; k++) {
        int c = lane + 32 * k;
        float r = 0.f;
#pragma unroll
        for (int i = 0; i < 4; i++) r += v[i][k] * (e[i] * inv);
        out[(size_t)warp * 128 + c] = r;
    }
}

// ------------------------------ host ------------------------------------------
#define GETSYM(ptr, sym) do { void* _t = nullptr; cudaGetSymbolAddress(&_t, sym); \
                              ptr = (decltype(ptr))_t; } while (0)

extern "C" void kernel_launch(void* const* d_in, const int* in_sizes, int n_in,
                              void* d_out, int out_size) {
    const int*   x_idx    = (const int*)d_in[0];
    const float* x_flt    = (const float*)d_in[1];
    const int*   ei_l     = (const int*)d_in[2];
    const int*   ei_r     = (const int*)d_in[3];
    const float* emb_aa   = (const float*)d_in[4];
    const float* emb_ss   = (const float*)d_in[5];
    const float* conv_W   = (const float*)d_in[6];
    const float* att_src  = (const float*)d_in[7];
    const float* att_dst  = (const float*)d_in[8];
    const float* conv_b   = (const float*)d_in[9];
    const float* lstm_Wih = (const float*)d_in[10];
    const float* lstm_Whh = (const float*)d_in[11];
    const float* lstm_bih = (const float*)d_in[12];
    const float* lstm_bhh = (const float*)d_in[13];
    const float* jk_att_W = (const float*)d_in[14];
    /* d_in[15] jk_att_b: constant over L, cancels in softmax */
    const float* dummy_W  = (const float*)d_in[16];
    const float* dummy_b  = (const float*)d_in[17];
    const float* fin_W    = (const float*)d_in[18];
    const float* fin_b    = (const float*)d_in[19];
    const float* last_W   = (const float*)d_in[20];

    const int N = in_sizes[0] / 2;
    const int E = in_sizes[2] / 2;

    float *X0L, *X0R, *XSL, *XSR, *MEAN, *XH, *ASRC, *ADST, *GI, *GB, *H, *C;
    float *SCF, *SCB, *JKL, *JKR, *SQL, *SQR, *OUTS, *WIHT, *WHHT, *BSUM;
    int *DEG, *IPL, *IPR, *CSL, *CSR2;
    GETSYM(X0L, g_X0L);  GETSYM(X0R, g_X0R);
    GETSYM(XSL, g_XSL);  GETSYM(XSR, g_XSR);
    GETSYM(MEAN, g_MEAN); GETSYM(XH, g_XH);
    GETSYM(ASRC, g_ASRC); GETSYM(ADST, g_ADST);
    GETSYM(GI, g_GI);    GETSYM(GB, g_GB);
    GETSYM(H, g_H);      GETSYM(C, g_C);
    GETSYM(SCF, g_SCF);  GETSYM(SCB, g_SCB);
    GETSYM(JKL, g_JKL);  GETSYM(JKR, g_JKR);
    GETSYM(SQL, g_SQL);  GETSYM(SQR, g_SQR);
    GETSYM(OUTS, g_OUTS);
    GETSYM(WIHT, g_WIHT); GETSYM(WHHT, g_WHHT); GETSYM(BSUM, g_BSUM);
    GETSYM(DEG, g_deg);
    GETSYM(IPL, g_indptrL); GETSYM(IPR, g_indptrR);
    GETSYM(CSL, g_csrL);    GETSYM(CSR2, g_csrR);

    const int TB = 256;
    // ---- CSR per branch (edges invariant across layers) ----
    for (int b = 0; b < 2; b++) {
        const int* ei = b ? ei_r : ei_l;
        int* ip = b ? IPR : IPL;
        int* cs = b ? CSR2 : CSL;
        k_deg_init<<<(N + TB - 1) / TB, TB>>>(DEG, N);
        k_deg_count<<<(E + TB - 1) / TB, TB>>>(DEG, ei + E, E);
        k_scan_excl<<<1, 1024>>>(DEG, ip, N);
        k_fill_self<<<(N + TB - 1) / TB, TB>>>(ip, cs, DEG, N);
        k_fill_edges<<<(E + TB - 1) / TB, TB>>>(ei, ei + E, DEG, cs, E);
    }

    // ---- input features ----
    k_init_x<<<(N * 128 + TB - 1) / TB, TB>>>(x_idx, x_flt, emb_aa, emb_ss, X0L, X0R, N);

    // ---- GAT layers ----
    const float* curL = X0L;
    const float* curR = X0R;
    for (int i = 0; i < 3; i++) {
        k_mean<<<(N * 128 + TB - 1) / TB, TB>>>(curL, curR, MEAN, N * 128);
        for (int b = 0; b < 2; b++) {
            const float* X = b ? curR : curL;
            float* Xnew = (b ? XSR : XSL) + (size_t)i * N * 128;
            int li = b * 3 + i;
            dim3 grid(256 / 128, (N + 127) / 128);
            gemm128<<<grid, 256>>>(X, conv_W + (size_t)li * 128 * 256,
                                   nullptr, nullptr, XH, N, 256, 128, 0);
            k_att<<<(N * 32 + 127) / 128, 128>>>(XH, att_src + li * 256, att_dst + li * 256,
                                                 ASRC, ADST, N);
            k_gat_agg<<<(N * 32 + 127) / 128, 128>>>(XH, b ? IPR : IPL, b ? CSR2 : CSL,
                                                     ASRC, ADST, MEAN, conv_b + li * 128,
                                                     Xnew, N);
        }
        curL = XSL + (size_t)i * N * 128;
        curR = XSR + (size_t)i * N * 128;
    }

    // ---- LSTM weight prep ----
    k_bsum<<<(4 * 768 + TB - 1) / TB, TB>>>(lstm_bih, lstm_bhh, BSUM, 4 * 768);
    k_transpose_w<<<(4 * 768 * 128 + TB - 1) / TB, TB>>>(lstm_Wih, WIHT, 128, 4 * 768 * 128);
    k_transpose_w<<<(4 * 768 * 192 + TB - 1) / TB, TB>>>(lstm_Whh, WHHT, 192, 4 * 768 * 192);

    // ---- JK bi-LSTM per branch ----
    for (int b = 0; b < 2; b++) {
        const float* XS = b ? XSR : XSL;
        for (int dir = 0; dir < 2; dir++) {
            int bd = b * 2 + dir;
            float* SC = dir ? SCB : SCF;
            // GI[l] = xs[l] @ Wih^T + (bih+bhh), all 3 layers batched (M = 3N)
            {
                dim3 grid(768 / 128, (3 * N + 127) / 128);
                gemm128<<<grid, 256>>>(XS, WIHT + (size_t)bd * 128 * 768, nullptr,
                                       BSUM + bd * 768, GI, 3 * N, 768, 128, 2);
            }
            k_zero<<<(N * 192 + TB - 1) / TB, TB>>>(H, N * 192);
            k_zero<<<(N * 192 + TB - 1) / TB, TB>>>(C, N * 192);
            const float* wseg = jk_att_W + b * 384 + dir * 192;
            for (int st = 0; st < 3; st++) {
                int t = dir ? (2 - st) : st;
                const float* G;
                if (st == 0) {
                    G = GI + (size_t)t * N * 768;  // h == 0: gates are GI directly
                } else {
                    dim3 grid(768 / 128, (N + 127) / 128);
                    gemm128<<<grid, 256>>>(H, WHHT + (size_t)bd * 192 * 768,
                                           GI + (size_t)t * N * 768, nullptr,
                                           GB, N, 768, 192, 1);
                    G = GB;
                }
                k_lstm_cell<<<(N * 192 + TB - 1) / TB, TB>>>(G, H, C, N);
                k_lstm_score<<<(N * 32 + 127) / 128, 128>>>(H, wseg, SC + (size_t)t * N, N);
            }
        }
        k_jk<<<(N * 128 + TB - 1) / TB, TB>>>(XS, SCF, SCB, b ? JKR : JKL, N);
    }

    // ---- heads ----
    {
        dim3 grid(1, (N + 127) / 128);
        gemm128<<<grid, 256>>>(JKL, dummy_W, nullptr, dummy_b, SQL, N, 128, 128, 2);
        gemm128<<<grid, 256>>>(JKR, dummy_W + 128 * 128, nullptr, dummy_b + 128, SQR, N, 128, 128, 2);
        const float* feats[4] = {JKL, SQL, JKR, SQR};
        for (int i = 0; i < 4; i++) {
            gemm128<<<grid, 256>>>(feats[i], fin_W + (size_t)i * 128 * 128, nullptr,
                                   fin_b + i * 128, OUTS + (size_t)i * N * 128,
                                   N, 128, 128, 2);
        }
    }
    k_final<<<(N * 32 + 127) / 128, 128>>>(OUTS, last_W, (float*)d_out, N);
}

// round 6
// speedup vs baseline: 2.2970x; 2.2970x over previous
#include <cuda_runtime.h>
#include <math.h>
#include <stdint.h>

#define NMAX 100000
#define EMAX 800000
#define ENMAX (NMAX + EMAX)

// ------------------------- static scratch (no allocs allowed) ----------------
__device__ float g_X0L[NMAX * 128];
__device__ float g_X0R[NMAX * 128];
__device__ float g_XSL[3 * NMAX * 128];
__device__ float g_XSR[3 * NMAX * 128];
__device__ float g_MEAN[NMAX * 128];
__device__ float g_XH[NMAX * 256];
__device__ float g_ASRC[NMAX * 2];
__device__ float g_ADST[NMAX * 2];
__device__ float g_GI[3 * NMAX * 768];
__device__ float g_GB[NMAX * 768];
__device__ float g_H[NMAX * 192];
__device__ float g_C[NMAX * 192];
__device__ float g_SCF[3 * NMAX];
__device__ float g_SCB[3 * NMAX];
__device__ float g_JKL[NMAX * 128];
__device__ float g_JKR[NMAX * 128];
__device__ float g_SQL[NMAX * 128];
__device__ float g_SQR[NMAX * 128];
__device__ float g_OUTS[4 * NMAX * 128];
__device__ float g_CWT[6 * 256 * 128];   // conv_W transposed  [mat][N=256][K=128]
__device__ float g_DWT[2 * 128 * 128];   // dummy_W transposed
__device__ float g_FWT[4 * 128 * 128];   // fin_W transposed
__device__ float g_BSUM[4 * 768];
__device__ int   g_deg[NMAX];            // also reused as fill cursor
__device__ int   g_part[520];
__device__ int   g_indptrL[NMAX + 1];
__device__ int   g_indptrR[NMAX + 1];
__device__ int   g_csrL[ENMAX];
__device__ int   g_csrR[ENMAX];

// ------------------------------ helpers --------------------------------------
__device__ __forceinline__ float wredsum(float v) {
#pragma unroll
    for (int o = 16; o; o >>= 1) v += __shfl_xor_sync(0xffffffffu, v, o);
    return v;
}
__device__ __forceinline__ float wredmax(float v) {
#pragma unroll
    for (int o = 16; o; o >>= 1) v = fmaxf(v, __shfl_xor_sync(0xffffffffu, v, o));
    return v;
}
__device__ __forceinline__ float sigf(float x) { return 1.0f / (1.0f + expf(-x)); }

__device__ __forceinline__ uint32_t tf32r(float x) {
    uint32_t r;
    asm("cvt.rna.tf32.f32 %0, %1;" : "=r"(r) : "f"(x));
    return r;
}
__device__ __forceinline__ void mma_tf32(float* d, const uint32_t* a, const uint32_t* b) {
    asm volatile(
        "mma.sync.aligned.m16n8k8.row.col.f32.tf32.tf32.f32 "
        "{%0,%1,%2,%3}, {%4,%5,%6,%7}, {%8,%9}, {%0,%1,%2,%3};"
        : "+f"(d[0]), "+f"(d[1]), "+f"(d[2]), "+f"(d[3])
        : "r"(a[0]), "r"(a[1]), "r"(a[2]), "r"(a[3]), "r"(b[0]), "r"(b[1]));
}

// ------------------------------ CSR build ------------------------------------
__global__ void k_deg_init(int* deg, int n) {
    int i = blockIdx.x * blockDim.x + threadIdx.x;
    if (i < n) deg[i] = 1;  // self loop
}
__global__ void k_deg_count(int* deg, const int* dst, int e) {
    int i = blockIdx.x * blockDim.x + threadIdx.x;
    if (i < e) atomicAdd(&deg[dst[i]], 1);
}
__global__ void k_scan1(const int* __restrict__ in, int* __restrict__ out,
                        int* __restrict__ part, int n) {
    __shared__ int sh[256];
    int tid = threadIdx.x;
    int i = blockIdx.x * 256 + tid;
    int v = (i < n) ? in[i] : 0;
    sh[tid] = v;
    __syncthreads();
    for (int off = 1; off < 256; off <<= 1) {
        int t = (tid >= off) ? sh[tid - off] : 0;
        __syncthreads();
        sh[tid] += t;
        __syncthreads();
    }
    if (i < n) out[i] = sh[tid] - v;
    if (tid == 255) part[blockIdx.x] = sh[255];
}
// serial-carry scan over partials (nb can exceed blockDim; loop with carry)
__global__ void k_scan2(int* part, int nb) {
    __shared__ int sh[512];
    __shared__ int carry;
    int tid = threadIdx.x;
    if (tid == 0) carry = 0;
    __syncthreads();
    for (int base = 0; base < nb; base += 512) {
        int i = base + tid;
        int v = (i < nb) ? part[i] : 0;
        sh[tid] = v;
        __syncthreads();
        for (int off = 1; off < 512; off <<= 1) {
            int t = (tid >= off) ? sh[tid - off] : 0;
            __syncthreads();
            sh[tid] += t;
            __syncthreads();
        }
        if (i < nb) part[i] = carry + sh[tid] - v;
        int tot = sh[511];
        __syncthreads();
        if (tid == 0) carry += tot;
        __syncthreads();
    }
    if (tid == 0) part[nb] = carry;
}
__global__ void k_scan3(int* out, const int* part, int n, int nb) {
    int i = blockIdx.x * 256 + threadIdx.x;
    if (i < n) out[i] += part[i >> 8];
    if (i == 0) out[n] = part[nb];
}
__global__ void k_fill_self(const int* indptr, int* csr, int* pos, int n) {
    int i = blockIdx.x * blockDim.x + threadIdx.x;
    if (i < n) {
        int p = indptr[i];
        csr[p] = i;
        pos[i] = p + 1;
    }
}
__global__ void k_fill_edges(const int* src, const int* dst, int* pos, int* csr, int e) {
    int i = blockIdx.x * blockDim.x + threadIdx.x;
    if (i < e) {
        int p = atomicAdd(&pos[dst[i]], 1);
        csr[p] = src[i];
    }
}

// ------------------------------ features -------------------------------------
__global__ void k_init_x(const int* __restrict__ x_idx, const float* __restrict__ x_flt,
                         const float* __restrict__ eaa, const float* __restrict__ ess,
                         float* __restrict__ XL, float* __restrict__ XR, int n) {
    int idx = blockIdx.x * blockDim.x + threadIdx.x;
    if (idx >= n * 128) return;
    int node = idx >> 7, c = idx & 127;
    float vl, vr;
    if (c < 123) {
        int i0 = x_idx[node * 2], i1 = x_idx[node * 2 + 1];
        vl = eaa[i0 * 123 + c] + ess[i1 * 123 + c];
        vr = eaa[26 * 123 + i0 * 123 + c] + ess[3 * 123 + i1 * 123 + c];
    } else {
        float f = x_flt[node * 5 + (c - 123)];
        vl = f; vr = f;
    }
    XL[idx] = vl;
    XR[idx] = vr;
}
__global__ void k_mean(const float* __restrict__ A, const float* __restrict__ B,
                       float* __restrict__ M, int total) {
    int i = blockIdx.x * blockDim.x + threadIdx.x;
    if (i < total) M[i] = 0.5f * (A[i] + B[i]);
}
__global__ void k_zero(float* p, int total) {
    int i = blockIdx.x * blockDim.x + threadIdx.x;
    if (i < total) p[i] = 0.0f;
}
// W: [mats][K][N] -> WT: [mats][N][K]
__global__ void k_transp(const float* __restrict__ W, float* __restrict__ WT,
                         int K, int N, int total) {
    int idx = blockIdx.x * blockDim.x + threadIdx.x;
    if (idx >= total) return;
    int per = K * N;
    int m = idx / per, rem = idx % per;
    int k = rem / N, n = rem % N;
    WT[(size_t)m * per + (size_t)n * K + k] = W[idx];
}
__global__ void k_bsum(const float* bih, const float* bhh, float* bsum, int total) {
    int i = blockIdx.x * blockDim.x + threadIdx.x;
    if (i < total) bsum[i] = bih[i] + bhh[i];
}

// --------------- tensor-core GEMM (mma.sync tf32, 128x128 tile) --------------
// C[M,N] = A[M,K] @ Bt[N,K]^T  (+ Dm if flags&1) (+ bias if flags&2)
// K % 32 == 0, N % 128 == 0. A,Bt row-major fp32.
__global__ void __launch_bounds__(256)
gemm_mma(const float* __restrict__ A, const float* __restrict__ Bt,
         const float* __restrict__ Dm, const float* __restrict__ bias,
         float* __restrict__ C, int M, int N, int K, int flags) {
    __shared__ uint32_t As[128][36];   // 32 used cols, pad 36 -> conflict-free frags
    __shared__ uint32_t Bs[128][36];
    const int tid = threadIdx.x;
    const int lane = tid & 31, wid = tid >> 5;
    const int wr = wid >> 2, wc = wid & 3;         // 2 x 4 warp grid
    const int g = lane >> 2, q = lane & 3;
    const int bm = blockIdx.y * 128, bn = blockIdx.x * 128;

    float acc[4][4][4];
#pragma unroll
    for (int i = 0; i < 4; i++)
#pragma unroll
        for (int j = 0; j < 4; j++)
#pragma unroll
            for (int k = 0; k < 4; k++) acc[i][j][k] = 0.0f;

    for (int k0 = 0; k0 < K; k0 += 32) {
        __syncthreads();
#pragma unroll
        for (int i = 0; i < 4; i++) {
            int idx = tid + i * 256;
            int r = idx >> 3, c4 = (idx & 7) * 4;
            int gr = bm + r;
            float4 v = make_float4(0.f, 0.f, 0.f, 0.f);
            if (gr < M) v = *(const float4*)(A + (size_t)gr * K + k0 + c4);
            As[r][c4 + 0] = tf32r(v.x);
            As[r][c4 + 1] = tf32r(v.y);
            As[r][c4 + 2] = tf32r(v.z);
            As[r][c4 + 3] = tf32r(v.w);
        }
#pragma unroll
        for (int i = 0; i < 4; i++) {
            int idx = tid + i * 256;
            int r = idx >> 3, c4 = (idx & 7) * 4;
            float4 v = *(const float4*)(Bt + (size_t)(bn + r) * K + k0 + c4);
            Bs[r][c4 + 0] = tf32r(v.x);
            Bs[r][c4 + 1] = tf32r(v.y);
            Bs[r][c4 + 2] = tf32r(v.z);
            Bs[r][c4 + 3] = tf32r(v.w);
        }
        __syncthreads();
#pragma unroll
        for (int ks = 0; ks < 4; ks++) {
            const int kk = ks * 8;
            uint32_t a[4][4], b[4][2];
#pragma unroll
            for (int mt = 0; mt < 4; mt++) {
                int r = wr * 64 + mt * 16 + g;
                a[mt][0] = As[r][kk + q];
                a[mt][1] = As[r + 8][kk + q];
                a[mt][2] = As[r][kk + q + 4];
                a[mt][3] = As[r + 8][kk + q + 4];
            }
#pragma unroll
            for (int nt = 0; nt < 4; nt++) {
                int c = wc * 32 + nt * 8 + g;
                b[nt][0] = Bs[c][kk + q];
                b[nt][1] = Bs[c][kk + q + 4];
            }
#pragma unroll
            for (int mt = 0; mt < 4; mt++)
#pragma unroll
                for (int nt = 0; nt < 4; nt++)
                    mma_tf32(acc[mt][nt], a[mt], b[nt]);
        }
    }

    // epilogue: c0,c1 -> (row, 2q / 2q+1); c2,c3 -> (row+8, ...)
#pragma unroll
    for (int mt = 0; mt < 4; mt++) {
        int r0 = bm + wr * 64 + mt * 16 + g;
        int r1 = r0 + 8;
#pragma unroll
        for (int nt = 0; nt < 4; nt++) {
            int c0 = bn + wc * 32 + nt * 8 + 2 * q;
            float bx = 0.f, by = 0.f;
            if (flags & 2) { bx = bias[c0]; by = bias[c0 + 1]; }
            if (r0 < M) {
                float vx = acc[mt][nt][0] + bx;
                float vy = acc[mt][nt][1] + by;
                if (flags & 1) {
                    const float* dp = Dm + (size_t)r0 * N + c0;
                    vx += dp[0]; vy += dp[1];
                }
                *(float2*)(C + (size_t)r0 * N + c0) = make_float2(vx, vy);
            }
            if (r1 < M) {
                float vx = acc[mt][nt][2] + bx;
                float vy = acc[mt][nt][3] + by;
                if (flags & 1) {
                    const float* dp = Dm + (size_t)r1 * N + c0;
                    vx += dp[0]; vy += dp[1];
                }
                *(float2*)(C + (size_t)r1 * N + c0) = make_float2(vx, vy);
            }
        }
    }
}

// ------------------------------ GAT ------------------------------------------
__global__ void k_att(const float* __restrict__ XH, const float* __restrict__ ws,
                      const float* __restrict__ wd, float* __restrict__ asrc,
                      float* __restrict__ adst, int n) {
    int warp = (blockIdx.x * blockDim.x + threadIdx.x) >> 5;
    int lane = threadIdx.x & 31;
    if (warp >= n) return;
    const float* row = XH + (size_t)warp * 256;
    float s0 = 0, s1 = 0, d0 = 0, d1 = 0;
#pragma unroll
    for (int k = 0; k < 4; k++) {
        int c = lane + 32 * k;
        float x0 = row[c], x1 = row[128 + c];
        s0 += x0 * ws[c];  s1 += x1 * ws[128 + c];
        d0 += x0 * wd[c];  d1 += x1 * wd[128 + c];
    }
    s0 = wredsum(s0); s1 = wredsum(s1); d0 = wredsum(d0); d1 = wredsum(d1);
    if (lane == 0) {
        asrc[warp * 2] = s0; asrc[warp * 2 + 1] = s1;
        adst[warp * 2] = d0; adst[warp * 2 + 1] = d1;
    }
}

__global__ void k_gat_agg(const float* __restrict__ XH, const int* __restrict__ indptr,
                          const int* __restrict__ csr, const float* __restrict__ asrc,
                          const float* __restrict__ adst, const float* __restrict__ mean,
                          const float* __restrict__ bias, float* __restrict__ Xout, int n) {
    int warp = (blockIdx.x * blockDim.x + threadIdx.x) >> 5;
    int lane = threadIdx.x & 31;
    if (warp >= n) return;
    int beg = indptr[warp], end = indptr[warp + 1];
    float ad0 = adst[warp * 2], ad1 = adst[warp * 2 + 1];

    float m0 = -1e30f, m1 = -1e30f;
    for (int j = beg + lane; j < end; j += 32) {
        int s = csr[j];
        float e0 = asrc[s * 2] + ad0;     e0 = (e0 > 0.f) ? e0 : 0.2f * e0;
        float e1 = asrc[s * 2 + 1] + ad1; e1 = (e1 > 0.f) ? e1 : 0.2f * e1;
        m0 = fmaxf(m0, e0); m1 = fmaxf(m1, e1);
    }
    m0 = wredmax(m0); m1 = wredmax(m1);

    float d0 = 0.f, d1 = 0.f;
    for (int j = beg + lane; j < end; j += 32) {
        int s = csr[j];
        float e0 = asrc[s * 2] + ad0;     e0 = (e0 > 0.f) ? e0 : 0.2f * e0;
        float e1 = asrc[s * 2 + 1] + ad1; e1 = (e1 > 0.f) ? e1 : 0.2f * e1;
        d0 += expf(e0 - m0); d1 += expf(e1 - m1);
    }
    d0 = wredsum(d0); d1 = wredsum(d1);
    float inv0 = 1.0f / (d0 + 1e-16f), inv1 = 1.0f / (d1 + 1e-16f);

    float acc[8];
#pragma unroll
    for (int k = 0; k < 8; k++) acc[k] = 0.f;
    for (int j = beg; j < end; j++) {
        int s = csr[j];
        float e0 = asrc[s * 2] + ad0;     e0 = (e0 > 0.f) ? e0 : 0.2f * e0;
        float e1 = asrc[s * 2 + 1] + ad1; e1 = (e1 > 0.f) ? e1 : 0.2f * e1;
        float w0 = expf(e0 - m0) * inv0;
        float w1 = expf(e1 - m1) * inv1;
        const float* row = XH + (size_t)s * 256;
#pragma unroll
        for (int k = 0; k < 4; k++) {
            int c = lane + 32 * k;
            acc[k]     += row[c] * w0;
            acc[k + 4] += row[128 + c] * w1;
        }
    }
#pragma unroll
    for (int k = 0; k < 4; k++) {
        int c = lane + 32 * k;
        float v = 0.5f * (acc[k] + acc[k + 4]) + bias[c];
        v = (v > 0.f) ? v : 0.f;
        Xout[(size_t)warp * 128 + c] = mean[(size_t)warp * 128 + c] + v;
    }
}

// ------------------------------ LSTM / JK ------------------------------------
__global__ void k_lstm_cell(const float* __restrict__ G, float* __restrict__ H,
                            float* __restrict__ Cc, int n) {
    int idx = blockIdx.x * blockDim.x + threadIdx.x;
    if (idx >= n * 192) return;
    int node = idx / 192, u = idx - node * 192;
    const float* g = G + (size_t)node * 768;
    float gi = g[u], gf = g[192 + u], gg = g[384 + u], go = g[576 + u];
    float c = Cc[idx];
    c = sigf(gf) * c + sigf(gi) * tanhf(gg);
    H[idx] = sigf(go) * tanhf(c);
    Cc[idx] = c;
}
__global__ void k_lstm_score(const float* __restrict__ H, const float* __restrict__ w,
                             float* __restrict__ sc, int n) {
    int warp = (blockIdx.x * blockDim.x + threadIdx.x) >> 5;
    int lane = threadIdx.x & 31;
    if (warp >= n) return;
    float p = 0.f;
#pragma unroll
    for (int k = 0; k < 6; k++) {
        int u = lane + 32 * k;
        p += H[(size_t)warp * 192 + u] * w[u];
    }
    p = wredsum(p);
    if (lane == 0) sc[warp] = p;
}
__global__ void k_jk(const float* __restrict__ XS, const float* __restrict__ SCF,
                     const float* __restrict__ SCB, float* __restrict__ JK, int n) {
    int idx = blockIdx.x * blockDim.x + threadIdx.x;
    if (idx >= n * 128) return;
    int node = idx >> 7;
    float s0 = SCF[node] + SCB[node];
    float s1 = SCF[n + node] + SCB[n + node];
    float s2 = SCF[2 * n + node] + SCB[2 * n + node];
    float m = fmaxf(s0, fmaxf(s1, s2));
    float e0 = expf(s0 - m), e1 = expf(s1 - m), e2 = expf(s2 - m);
    float inv = 1.0f / (e0 + e1 + e2);
    float v = e0 * XS[idx] + e1 * XS[(size_t)n * 128 + idx] + e2 * XS[(size_t)2 * n * 128 + idx];
    JK[idx] = v * inv;
}

// ------------------------------ final ----------------------------------------
__global__ void k_final(const float* __restrict__ OUTS, const float* __restrict__ lw,
                        float* __restrict__ out, int n) {
    int warp = (blockIdx.x * blockDim.x + threadIdx.x) >> 5;
    int lane = threadIdx.x & 31;
    if (warp >= n) return;
    float v[4][4];
    float s[4];
#pragma unroll
    for (int i = 0; i < 4; i++) {
        const float* row = OUTS + (size_t)i * n * 128 + (size_t)warp * 128;
        float p = 0.f;
#pragma unroll
        for (int k = 0; k < 4; k++) {
            int c = lane + 32 * k;
            v[i][k] = row[c];
            p += v[i][k] * lw[c];
        }
        s[i] = wredsum(p);
    }
    float m = fmaxf(fmaxf(s[0], s[1]), fmaxf(s[2], s[3]));
    float e[4];
    float den = 0.f;
#pragma unroll
    for (int i = 0; i < 4; i++) { e[i] = expf(s[i] - m); den += e[i]; }
    float inv = 1.0f / den;
#pragma unroll
    for (int k = 0; k < 4; k++) {
        int c = lane + 32 * k;
        float r = 0.f;
#pragma unroll
        for (int i = 0; i < 4; i++) r += v[i][k] * (e[i] * inv);
        out[(size_t)warp * 128 + c] = r;
    }
}

// ------------------------------ host ------------------------------------------
#define GETSYM(ptr, sym) do { void* _t = nullptr; cudaGetSymbolAddress(&_t, sym); \
                              ptr = (decltype(ptr))_t; } while (0)

static inline void launch_gemm(const float* A, const float* Bt, const float* Dm,
                               const float* bias, float* C, int M, int N, int K, int flags) {
    dim3 grid(N / 128, (M + 127) / 128);
    gemm_mma<<<grid, 256>>>(A, Bt, Dm, bias, C, M, N, K, flags);
}

extern "C" void kernel_launch(void* const* d_in, const int* in_sizes, int n_in,
                              void* d_out, int out_size) {
    const int*   x_idx    = (const int*)d_in[0];
    const float* x_flt    = (const float*)d_in[1];
    const int*   ei_l     = (const int*)d_in[2];
    const int*   ei_r     = (const int*)d_in[3];
    const float* emb_aa   = (const float*)d_in[4];
    const float* emb_ss   = (const float*)d_in[5];
    const float* conv_W   = (const float*)d_in[6];
    const float* att_src  = (const float*)d_in[7];
    const float* att_dst  = (const float*)d_in[8];
    const float* conv_b   = (const float*)d_in[9];
    const float* lstm_Wih = (const float*)d_in[10];
    const float* lstm_Whh = (const float*)d_in[11];
    const float* lstm_bih = (const float*)d_in[12];
    const float* lstm_bhh = (const float*)d_in[13];
    const float* jk_att_W = (const float*)d_in[14];
    /* d_in[15] jk_att_b: constant over L, cancels in softmax */
    const float* dummy_W  = (const float*)d_in[16];
    const float* dummy_b  = (const float*)d_in[17];
    const float* fin_W    = (const float*)d_in[18];
    const float* fin_b    = (const float*)d_in[19];
    const float* last_W   = (const float*)d_in[20];

    const int N = in_sizes[0] / 2;
    const int E = in_sizes[2] / 2;

    float *X0L, *X0R, *XSL, *XSR, *MEAN, *XH, *ASRC, *ADST, *GI, *GB, *H, *C;
    float *SCF, *SCB, *JKL, *JKR, *SQL, *SQR, *OUTS, *CWT, *DWT, *FWT, *BSUM;
    int *DEG, *PART, *IPL, *IPR, *CSL, *CSR2;
    GETSYM(X0L, g_X0L);  GETSYM(X0R, g_X0R);
    GETSYM(XSL, g_XSL);  GETSYM(XSR, g_XSR);
    GETSYM(MEAN, g_MEAN); GETSYM(XH, g_XH);
    GETSYM(ASRC, g_ASRC); GETSYM(ADST, g_ADST);
    GETSYM(GI, g_GI);    GETSYM(GB, g_GB);
    GETSYM(H, g_H);      GETSYM(C, g_C);
    GETSYM(SCF, g_SCF);  GETSYM(SCB, g_SCB);
    GETSYM(JKL, g_JKL);  GETSYM(JKR, g_JKR);
    GETSYM(SQL, g_SQL);  GETSYM(SQR, g_SQR);
    GETSYM(OUTS, g_OUTS);
    GETSYM(CWT, g_CWT);  GETSYM(DWT, g_DWT);  GETSYM(FWT, g_FWT);
    GETSYM(BSUM, g_BSUM);
    GETSYM(DEG, g_deg);  GETSYM(PART, g_part);
    GETSYM(IPL, g_indptrL); GETSYM(IPR, g_indptrR);
    GETSYM(CSL, g_csrL);    GETSYM(CSR2, g_csrR);

    const int TB = 256;
    const int NB = (N + 255) / 256;
    // ---- CSR per branch (edges invariant across layers) ----
    for (int b = 0; b < 2; b++) {
        const int* ei = b ? ei_r : ei_l;
        int* ip = b ? IPR : IPL;
        int* cs = b ? CSR2 : CSL;
        k_deg_init<<<(N + TB - 1) / TB, TB>>>(DEG, N);
        k_deg_count<<<(E + TB - 1) / TB, TB>>>(DEG, ei + E, E);
        k_scan1<<<NB, 256>>>(DEG, ip, PART, N);
        k_scan2<<<1, 512>>>(PART, NB);
        k_scan3<<<NB, 256>>>(ip, PART, N, NB);
        k_fill_self<<<(N + TB - 1) / TB, TB>>>(ip, cs, DEG, N);
        k_fill_edges<<<(E + TB - 1) / TB, TB>>>(ei, ei + E, DEG, cs, E);
    }

    // ---- weight prep (transposes to [N,K] K-major for mma B operand) ----
    k_transp<<<(6 * 128 * 256 + TB - 1) / TB, TB>>>(conv_W, CWT, 128, 256, 6 * 128 * 256);
    k_transp<<<(2 * 128 * 128 + TB - 1) / TB, TB>>>(dummy_W, DWT, 128, 128, 2 * 128 * 128);
    k_transp<<<(4 * 128 * 128 + TB - 1) / TB, TB>>>(fin_W, FWT, 128, 128, 4 * 128 * 128);
    k_bsum<<<(4 * 768 + TB - 1) / TB, TB>>>(lstm_bih, lstm_bhh, BSUM, 4 * 768);

    // ---- input features ----
    k_init_x<<<(N * 128 + TB - 1) / TB, TB>>>(x_idx, x_flt, emb_aa, emb_ss, X0L, X0R, N);

    // ---- GAT layers ----
    const float* curL = X0L;
    const float* curR = X0R;
    for (int i = 0; i < 3; i++) {
        k_mean<<<(N * 128 + TB - 1) / TB, TB>>>(curL, curR, MEAN, N * 128);
        for (int b = 0; b < 2; b++) {
            const float* X = b ? curR : curL;
            float* Xnew = (b ? XSR : XSL) + (size_t)i * N * 128;
            int li = b * 3 + i;
            launch_gemm(X, CWT + (size_t)li * 256 * 128, nullptr, nullptr, XH, N, 256, 128, 0);
            k_att<<<(N * 32 + 127) / 128, 128>>>(XH, att_src + li * 256, att_dst + li * 256,
                                                 ASRC, ADST, N);
            k_gat_agg<<<(N * 32 + 127) / 128, 128>>>(XH, b ? IPR : IPL, b ? CSR2 : CSL,
                                                     ASRC, ADST, MEAN, conv_b + li * 128,
                                                     Xnew, N);
        }
        curL = XSL + (size_t)i * N * 128;
        curR = XSR + (size_t)i * N * 128;
    }

    // ---- JK bi-LSTM per branch ----
    for (int b = 0; b < 2; b++) {
        const float* XS = b ? XSR : XSL;
        for (int dir = 0; dir < 2; dir++) {
            int bd = b * 2 + dir;
            float* SC = dir ? SCB : SCF;
            // GI[l] = xs[l] @ Wih^T + (bih+bhh), all 3 layers batched (M = 3N)
            // lstm_Wih[bd] is [768,128] row-major == [N,K] K-major: use directly
            launch_gemm(XS, lstm_Wih + (size_t)bd * 768 * 128, nullptr,
                        BSUM + bd * 768, GI, 3 * N, 768, 128, 2);
            k_zero<<<(N * 192 + TB - 1) / TB, TB>>>(H, N * 192);
            k_zero<<<(N * 192 + TB - 1) / TB, TB>>>(C, N * 192);
            const float* wseg = jk_att_W + b * 384 + dir * 192;
            for (int st = 0; st < 3; st++) {
                int t = dir ? (2 - st) : st;
                const float* G;
                if (st == 0) {
                    G = GI + (size_t)t * N * 768;  // h == 0: gates are GI directly
                } else {
                    launch_gemm(H, lstm_Whh + (size_t)bd * 768 * 192,
                                GI + (size_t)t * N * 768, nullptr, GB, N, 768, 192, 1);
                    G = GB;
                }
                k_lstm_cell<<<(N * 192 + TB - 1) / TB, TB>>>(G, H, C, N);
                k_lstm_score<<<(N * 32 + 127) / 128, 128>>>(H, wseg, SC + (size_t)t * N, N);
            }
        }
        k_jk<<<(N * 128 + TB - 1) / TB, TB>>>(XS, SCF, SCB, b ? JKR : JKL, N);
    }

    // ---- heads ----
    launch_gemm(JKL, DWT,               nullptr, dummy_b,       SQL, N, 128, 128, 2);
    launch_gemm(JKR, DWT + 128 * 128,   nullptr, dummy_b + 128, SQR, N, 128, 128, 2);
    {
        const float* feats[4] = {JKL, SQL, JKR, SQR};
        for (int i = 0; i < 4; i++) {
            launch_gemm(feats[i], FWT + (size_t)i * 128 * 128, nullptr,
                        fin_b + i * 128, OUTS + (size_t)i * N * 128, N, 128, 128, 2);
        }
    }
    k_final<<<(N * 32 + 127) / 128, 128>>>(OUTS, last_W, (float*)d_out, N);
}

// round 7
// speedup vs baseline: 3.3765x; 1.4699x over previous
#include <cuda_runtime.h>
#include <math.h>
#include <stdint.h>

#define NMAX 100000
#define EMAX 800000
#define ENMAX (NMAX + EMAX)

// ------------------------- static scratch (no allocs allowed) ----------------
__device__ float g_X0L[NMAX * 128];
__device__ float g_X0R[NMAX * 128];
__device__ float g_XSL[3 * NMAX * 128];
__device__ float g_XSR[3 * NMAX * 128];
__device__ float g_XH[NMAX * 256];
__device__ float g_ASRC[NMAX * 2];
__device__ float g_ADST[NMAX * 2];
__device__ float g_HA[NMAX * 192];
__device__ float g_HB[NMAX * 192];
__device__ float g_CC[NMAX * 192];
__device__ float g_SCF[3 * NMAX];
__device__ float g_SCB[3 * NMAX];
__device__ float g_JKL[NMAX * 128];
__device__ float g_JKR[NMAX * 128];
__device__ float g_SQL[NMAX * 128];
__device__ float g_SQR[NMAX * 128];
__device__ float g_OUTS[4 * NMAX * 128];
__device__ float g_CWT[6 * 256 * 128];   // conv_W transposed  [mat][N=256][K=128]
__device__ float g_DWT[2 * 128 * 128];   // dummy_W transposed
__device__ float g_FWT[4 * 128 * 128];   // fin_W transposed
__device__ float g_WIHP[4 * 768 * 128];  // Wih gate-interleaved [bd][4u+g][128]
__device__ float g_WHHP[4 * 768 * 192];  // Whh gate-interleaved
__device__ float g_BSUMP[4 * 768];       // bih+bhh gate-interleaved
__device__ int   g_deg[NMAX];            // also reused as fill cursor
__device__ int   g_part[520];
__device__ int   g_indptrL[NMAX + 1];
__device__ int   g_indptrR[NMAX + 1];
__device__ int   g_csrL[ENMAX];
__device__ int   g_csrR[ENMAX];

// ------------------------------ helpers --------------------------------------
__device__ __forceinline__ float wredsum(float v) {
#pragma unroll
    for (int o = 16; o; o >>= 1) v += __shfl_xor_sync(0xffffffffu, v, o);
    return v;
}
__device__ __forceinline__ float wredmax(float v) {
#pragma unroll
    for (int o = 16; o; o >>= 1) v = fmaxf(v, __shfl_xor_sync(0xffffffffu, v, o));
    return v;
}
__device__ __forceinline__ float sigf(float x) { return 1.0f / (1.0f + expf(-x)); }

__device__ __forceinline__ uint32_t tf32r(float x) {
    uint32_t r;
    asm("cvt.rna.tf32.f32 %0, %1;" : "=r"(r) : "f"(x));
    return r;
}
__device__ __forceinline__ void mma_tf32(float* d, const uint32_t* a, const uint32_t* b) {
    asm volatile(
        "mma.sync.aligned.m16n8k8.row.col.f32.tf32.tf32.f32 "
        "{%0,%1,%2,%3}, {%4,%5,%6,%7}, {%8,%9}, {%0,%1,%2,%3};"
        : "+f"(d[0]), "+f"(d[1]), "+f"(d[2]), "+f"(d[3])
        : "r"(a[0]), "r"(a[1]), "r"(a[2]), "r"(a[3]), "r"(b[0]), "r"(b[1]));
}
__device__ __forceinline__ uint32_t su32(const void* p) {
    uint32_t a;
    asm("{ .reg .u64 t; cvta.to.shared.u64 t, %1; cvt.u32.u64 %0, t; }" : "=r"(a) : "l"(p));
    return a;
}
__device__ __forceinline__ void cpasync16(uint32_t dst, const void* src, int srcsize) {
    asm volatile("cp.async.ca.shared.global [%0], [%1], 16, %2;"
                 :: "r"(dst), "l"(src), "r"(srcsize));
}
__device__ __forceinline__ void cpacommit() { asm volatile("cp.async.commit_group;"); }
template <int n> __device__ __forceinline__ void cpawait() {
    asm volatile("cp.async.wait_group %0;" :: "n"(n));
}

// ------------------------------ CSR build ------------------------------------
__global__ void k_deg_init(int* deg, int n) {
    int i = blockIdx.x * blockDim.x + threadIdx.x;
    if (i < n) deg[i] = 1;  // self loop
}
__global__ void k_deg_count(int* deg, const int* dst, int e) {
    int i = blockIdx.x * blockDim.x + threadIdx.x;
    if (i < e) atomicAdd(&deg[dst[i]], 1);
}
__global__ void k_scan1(const int* __restrict__ in, int* __restrict__ out,
                        int* __restrict__ part, int n) {
    __shared__ int sh[256];
    int tid = threadIdx.x;
    int i = blockIdx.x * 256 + tid;
    int v = (i < n) ? in[i] : 0;
    sh[tid] = v;
    __syncthreads();
    for (int off = 1; off < 256; off <<= 1) {
        int t = (tid >= off) ? sh[tid - off] : 0;
        __syncthreads();
        sh[tid] += t;
        __syncthreads();
    }
    if (i < n) out[i] = sh[tid] - v;
    if (tid == 255) part[blockIdx.x] = sh[255];
}
__global__ void k_scan2(int* part, int nb) {
    __shared__ int sh[512];
    __shared__ int carry;
    int tid = threadIdx.x;
    if (tid == 0) carry = 0;
    __syncthreads();
    for (int base = 0; base < nb; base += 512) {
        int i = base + tid;
        int v = (i < nb) ? part[i] : 0;
        sh[tid] = v;
        __syncthreads();
        for (int off = 1; off < 512; off <<= 1) {
            int t = (tid >= off) ? sh[tid - off] : 0;
            __syncthreads();
            sh[tid] += t;
            __syncthreads();
        }
        if (i < nb) part[i] = carry + sh[tid] - v;
        int tot = sh[511];
        __syncthreads();
        if (tid == 0) carry += tot;
        __syncthreads();
    }
    if (tid == 0) part[nb] = carry;
}
__global__ void k_scan3(int* out, const int* part, int n, int nb) {
    int i = blockIdx.x * 256 + threadIdx.x;
    if (i < n) out[i] += part[i >> 8];
    if (i == 0) out[n] = part[nb];
}
__global__ void k_fill_self(const int* indptr, int* csr, int* pos, int n) {
    int i = blockIdx.x * blockDim.x + threadIdx.x;
    if (i < n) {
        int p = indptr[i];
        csr[p] = i;
        pos[i] = p + 1;
    }
}
__global__ void k_fill_edges(const int* src, const int* dst, int* pos, int* csr, int e) {
    int i = blockIdx.x * blockDim.x + threadIdx.x;
    if (i < e) {
        int p = atomicAdd(&pos[dst[i]], 1);
        csr[p] = src[i];
    }
}

// ------------------------------ features / prep ------------------------------
__global__ void k_init_x(const int* __restrict__ x_idx, const float* __restrict__ x_flt,
                         const float* __restrict__ eaa, const float* __restrict__ ess,
                         float* __restrict__ XL, float* __restrict__ XR, int n) {
    int idx = blockIdx.x * blockDim.x + threadIdx.x;
    if (idx >= n * 128) return;
    int node = idx >> 7, c = idx & 127;
    float vl, vr;
    if (c < 123) {
        int i0 = x_idx[node * 2], i1 = x_idx[node * 2 + 1];
        vl = eaa[i0 * 123 + c] + ess[i1 * 123 + c];
        vr = eaa[26 * 123 + i0 * 123 + c] + ess[3 * 123 + i1 * 123 + c];
    } else {
        float f = x_flt[node * 5 + (c - 123)];
        vl = f; vr = f;
    }
    XL[idx] = vl;
    XR[idx] = vr;
}
__global__ void k_zero(float* p, int total) {
    int i = blockIdx.x * blockDim.x + threadIdx.x;
    if (i < total) p[i] = 0.0f;
}
// W: [mats][K][N] -> WT: [mats][N][K]
__global__ void k_transp(const float* __restrict__ W, float* __restrict__ WT,
                         int K, int N, int total) {
    int idx = blockIdx.x * blockDim.x + threadIdx.x;
    if (idx >= total) return;
    int per = K * N;
    int m = idx / per, rem = idx % per;
    int k = rem / N, n = rem % N;
    WT[(size_t)m * per + (size_t)n * K + k] = W[idx];
}
// gate-interleave permute: out[bd][p][k] = in[bd][(p&3)*192 + (p>>2)][k]
__global__ void k_permw(const float* __restrict__ in, float* __restrict__ out,
                        int K, int total) {
    int idx = blockIdx.x * blockDim.x + threadIdx.x;
    if (idx >= total) return;
    int per = 768 * K;
    int bd = idx / per, rem = idx % per;
    int p = rem / K, k = rem % K;
    int orig = (p & 3) * 192 + (p >> 2);
    out[idx] = in[(size_t)bd * per + (size_t)orig * K + k];
}
__global__ void k_bsump(const float* bih, const float* bhh, float* out, int total) {
    int i = blockIdx.x * blockDim.x + threadIdx.x;
    if (i >= total) return;
    int bd = i / 768, p = i % 768;
    int orig = bd * 768 + (p & 3) * 192 + (p >> 2);
    out[i] = bih[orig] + bhh[orig];
}

// ---------- generic pipelined tf32 GEMM: C = A @ Bt^T (+bias) ----------------
// A [M,K] row-major fp32, Bt [N,K] row-major fp32. K%32==0, N%128==0.
#define GEMM_SMEM 73728
__global__ void __launch_bounds__(256)
gemm_mma(const float* __restrict__ A, const float* __restrict__ Bt,
         const float* __restrict__ bias, float* __restrict__ C,
         int M, int N, int K) {
    extern __shared__ float sm[];
    float (*As)[128][36] = (float(*)[128][36])sm;
    float (*Bs)[128][36] = (float(*)[128][36])(sm + 2 * 128 * 36);
    const int tid = threadIdx.x;
    const int lane = tid & 31, wid = tid >> 5;
    const int wr = wid >> 2, wc = wid & 3;
    const int g = lane >> 2, q = lane & 3;
    const int bm = blockIdx.y * 128, bn = blockIdx.x * 128;

    float acc[4][4][4];
#pragma unroll
    for (int i = 0; i < 4; i++)
#pragma unroll
        for (int j = 0; j < 4; j++)
#pragma unroll
            for (int k = 0; k < 4; k++) acc[i][j][k] = 0.0f;

    const int nch = K >> 5;
#pragma unroll
    for (int i = 0; i < 4; i++) {
        int idx = tid + i * 256;
        int r = idx >> 3, c4 = (idx & 7) * 4;
        cpasync16(su32(&As[0][r][c4]), A + (size_t)(bm + r) * K + c4, (bm + r) < M ? 16 : 0);
        cpasync16(su32(&Bs[0][r][c4]), Bt + (size_t)(bn + r) * K + c4, 16);
    }
    cpacommit();

    for (int ch = 0; ch < nch; ch++) {
        const int buf = ch & 1;
        if (ch + 1 < nch) {
            int k0 = (ch + 1) * 32, nb = (ch + 1) & 1;
#pragma unroll
            for (int i = 0; i < 4; i++) {
                int idx = tid + i * 256;
                int r = idx >> 3, c4 = (idx & 7) * 4;
                cpasync16(su32(&As[nb][r][c4]), A + (size_t)(bm + r) * K + k0 + c4,
                          (bm + r) < M ? 16 : 0);
                cpasync16(su32(&Bs[nb][r][c4]), Bt + (size_t)(bn + r) * K + k0 + c4, 16);
            }
            cpacommit();
            cpawait<1>();
        } else {
            cpawait<0>();
        }
        __syncthreads();
#pragma unroll
        for (int ks = 0; ks < 4; ks++) {
            const int kk = ks * 8;
            uint32_t a[4][4], b[4][2];
#pragma unroll
            for (int mt = 0; mt < 4; mt++) {
                int r = wr * 64 + mt * 16 + g;
                a[mt][0] = tf32r(As[buf][r][kk + q]);
                a[mt][1] = tf32r(As[buf][r + 8][kk + q]);
                a[mt][2] = tf32r(As[buf][r][kk + q + 4]);
                a[mt][3] = tf32r(As[buf][r + 8][kk + q + 4]);
            }
#pragma unroll
            for (int nt = 0; nt < 4; nt++) {
                int c = wc * 32 + nt * 8 + g;
                b[nt][0] = tf32r(Bs[buf][c][kk + q]);
                b[nt][1] = tf32r(Bs[buf][c][kk + q + 4]);
            }
#pragma unroll
            for (int mt = 0; mt < 4; mt++)
#pragma unroll
                for (int nt = 0; nt < 4; nt++)
                    mma_tf32(acc[mt][nt], a[mt], b[nt]);
        }
        __syncthreads();
    }

#pragma unroll
    for (int mt = 0; mt < 4; mt++) {
        int r0 = bm + wr * 64 + mt * 16 + g;
        int r1 = r0 + 8;
#pragma unroll
        for (int nt = 0; nt < 4; nt++) {
            int c0 = bn + wc * 32 + nt * 8 + 2 * q;
            float bx = 0.f, by = 0.f;
            if (bias) { bx = bias[c0]; by = bias[c0 + 1]; }
            if (r0 < M)
                *(float2*)(C + (size_t)r0 * N + c0) =
                    make_float2(acc[mt][nt][0] + bx, acc[mt][nt][1] + by);
            if (r1 < M)
                *(float2*)(C + (size_t)r1 * N + c0) =
                    make_float2(acc[mt][nt][2] + bx, acc[mt][nt][3] + by);
        }
    }
}

// ---------- fused LSTM timestep GEMM + cell + score --------------------------
// gates = X@Wih'^T + Hprev@Whh'^T + bsum' (gate-interleaved cols: 4u+{i,f,g,o})
// epilogue: c' = sig(f)c + sig(i)tanh(g); h = sig(o)tanh(c'); SC[row] += h.w
// nch2 = 6 for steps with Hprev (K2=192), 0 for first step (c=0, no H term).
__global__ void __launch_bounds__(256)
lstm_gemm(const float* __restrict__ X, const float* __restrict__ Wih,
          const float* __restrict__ Hprev, const float* __restrict__ Whh,
          const float* __restrict__ bsum, const float* __restrict__ wvec,
          float* __restrict__ Cmat, float* __restrict__ Hout,
          float* __restrict__ SC, int M, int nch2) {
    extern __shared__ float sm[];
    float (*As)[128][36] = (float(*)[128][36])sm;
    float (*Bs)[128][36] = (float(*)[128][36])(sm + 2 * 128 * 36);
    const int tid = threadIdx.x;
    const int lane = tid & 31, wid = tid >> 5;
    const int wr = wid >> 2, wc = wid & 3;
    const int g = lane >> 2, q = lane & 3;
    const int bm = blockIdx.y * 128, bn = blockIdx.x * 128;

    float acc[4][4][4];
#pragma unroll
    for (int i = 0; i < 4; i++)
#pragma unroll
        for (int j = 0; j < 4; j++)
#pragma unroll
            for (int k = 0; k < 4; k++) acc[i][j][k] = 0.0f;

    const int nch = 4 + nch2;
    // prologue: chunk 0 (always from X / Wih, stride 128)
#pragma unroll
    for (int i = 0; i < 4; i++) {
        int idx = tid + i * 256;
        int r = idx >> 3, c4 = (idx & 7) * 4;
        cpasync16(su32(&As[0][r][c4]), X + (size_t)(bm + r) * 128 + c4, (bm + r) < M ? 16 : 0);
        cpasync16(su32(&Bs[0][r][c4]), Wih + (size_t)(bn + r) * 128 + c4, 16);
    }
    cpacommit();

    for (int ch = 0; ch < nch; ch++) {
        const int buf = ch & 1;
        if (ch + 1 < nch) {
            int nc = ch + 1, nb = nc & 1;
            const float* Asrc; const float* Bsrc; int str, k0;
            if (nc < 4) { Asrc = X;     Bsrc = Wih; str = 128; k0 = nc * 32; }
            else        { Asrc = Hprev; Bsrc = Whh; str = 192; k0 = (nc - 4) * 32; }
#pragma unroll
            for (int i = 0; i < 4; i++) {
                int idx = tid + i * 256;
                int r = idx >> 3, c4 = (idx & 7) * 4;
                cpasync16(su32(&As[nb][r][c4]), Asrc + (size_t)(bm + r) * str + k0 + c4,
                          (bm + r) < M ? 16 : 0);
                cpasync16(su32(&Bs[nb][r][c4]), Bsrc + (size_t)(bn + r) * str + k0 + c4, 16);
            }
            cpacommit();
            cpawait<1>();
        } else {
            cpawait<0>();
        }
        __syncthreads();
#pragma unroll
        for (int ks = 0; ks < 4; ks++) {
            const int kk = ks * 8;
            uint32_t a[4][4], b[4][2];
#pragma unroll
            for (int mt = 0; mt < 4; mt++) {
                int r = wr * 64 + mt * 16 + g;
                a[mt][0] = tf32r(As[buf][r][kk + q]);
                a[mt][1] = tf32r(As[buf][r + 8][kk + q]);
                a[mt][2] = tf32r(As[buf][r][kk + q + 4]);
                a[mt][3] = tf32r(As[buf][r + 8][kk + q + 4]);
            }
#pragma unroll
            for (int nt = 0; nt < 4; nt++) {
                int c = wc * 32 + nt * 8 + g;
                b[nt][0] = tf32r(Bs[buf][c][kk + q]);
                b[nt][1] = tf32r(Bs[buf][c][kk + q + 4]);
            }
#pragma unroll
            for (int mt = 0; mt < 4; mt++)
#pragma unroll
                for (int nt = 0; nt < 4; nt++)
                    mma_tf32(acc[mt][nt], a[mt], b[nt]);
        }
        __syncthreads();
    }

    // fused epilogue: lane pair (q, q^1) jointly holds gates (i,f) / (g,o) of a unit
    const bool first = (nch2 == 0);
    float pr[4][2];
#pragma unroll
    for (int mt = 0; mt < 4; mt++) { pr[mt][0] = 0.f; pr[mt][1] = 0.f; }
#pragma unroll
    for (int nt = 0; nt < 4; nt++) {
        int c0 = bn + wc * 32 + nt * 8 + 2 * q;
        float b0 = bsum[c0], b1 = bsum[c0 + 1];
        int u = c0 >> 2;
        float wv = wvec[u];
#pragma unroll
        for (int mt = 0; mt < 4; mt++) {
            int r0 = bm + wr * 64 + mt * 16 + g, r1 = r0 + 8;
            float v0 = acc[mt][nt][0] + b0, v1 = acc[mt][nt][1] + b1;
            float w0 = acc[mt][nt][2] + b0, w1 = acc[mt][nt][3] + b1;
            float ov0 = __shfl_xor_sync(0xffffffffu, v0, 1);
            float ov1 = __shfl_xor_sync(0xffffffffu, v1, 1);
            float ow0 = __shfl_xor_sync(0xffffffffu, w0, 1);
            float ow1 = __shfl_xor_sync(0xffffffffu, w1, 1);
            if (!(q & 1)) {  // even lane: owns unit u; (i,f)=(v0,v1), (g,o)=(ov0,ov1)
                if (r0 < M) {
                    float cold = first ? 0.f : Cmat[(size_t)r0 * 192 + u];
                    float cn = sigf(v1) * cold + sigf(v0) * tanhf(ov0);
                    float h = sigf(ov1) * tanhf(cn);
                    Cmat[(size_t)r0 * 192 + u] = cn;
                    Hout[(size_t)r0 * 192 + u] = h;
                    pr[mt][0] += h * wv;
                }
                if (r1 < M) {
                    float cold = first ? 0.f : Cmat[(size_t)r1 * 192 + u];
                    float cn = sigf(w1) * cold + sigf(w0) * tanhf(ow0);
                    float h = sigf(ow1) * tanhf(cn);
                    Cmat[(size_t)r1 * 192 + u] = cn;
                    Hout[(size_t)r1 * 192 + u] = h;
                    pr[mt][1] += h * wv;
                }
            }
        }
    }
#pragma unroll
    for (int mt = 0; mt < 4; mt++) {
        float p0 = pr[mt][0] + __shfl_xor_sync(0xffffffffu, pr[mt][0], 2);
        float p1 = pr[mt][1] + __shfl_xor_sync(0xffffffffu, pr[mt][1], 2);
        if (q == 0) {
            int r0 = bm + wr * 64 + mt * 16 + g, r1 = r0 + 8;
            if (r0 < M) atomicAdd(SC + r0, p0);
            if (r1 < M) atomicAdd(SC + r1, p1);
        }
    }
}

// ------------------------------ GAT ------------------------------------------
__global__ void k_att(const float* __restrict__ XH, const float* __restrict__ ws,
                      const float* __restrict__ wd, float* __restrict__ asrc,
                      float* __restrict__ adst, int n) {
    int warp = (blockIdx.x * blockDim.x + threadIdx.x) >> 5;
    int lane = threadIdx.x & 31;
    if (warp >= n) return;
    const float* row = XH + (size_t)warp * 256;
    float s0 = 0, s1 = 0, d0 = 0, d1 = 0;
#pragma unroll
    for (int k = 0; k < 4; k++) {
        int c = lane + 32 * k;
        float x0 = row[c], x1 = row[128 + c];
        s0 += x0 * ws[c];  s1 += x1 * ws[128 + c];
        d0 += x0 * wd[c];  d1 += x1 * wd[128 + c];
    }
    s0 = wredsum(s0); s1 = wredsum(s1); d0 = wredsum(d0); d1 = wredsum(d1);
    if (lane == 0) {
        asrc[warp * 2] = s0; asrc[warp * 2 + 1] = s1;
        adst[warp * 2] = d0; adst[warp * 2 + 1] = d1;
    }
}

__global__ void k_gat_agg(const float* __restrict__ XH, const int* __restrict__ indptr,
                          const int* __restrict__ csr, const float* __restrict__ asrc,
                          const float* __restrict__ adst, const float* __restrict__ XL,
                          const float* __restrict__ XR, const float* __restrict__ bias,
                          float* __restrict__ Xout, int n) {
    int warp = (blockIdx.x * blockDim.x + threadIdx.x) >> 5;
    int lane = threadIdx.x & 31;
    if (warp >= n) return;
    int beg = indptr[warp], end = indptr[warp + 1];
    float ad0 = adst[warp * 2], ad1 = adst[warp * 2 + 1];

    float m0 = -1e30f, m1 = -1e30f;
    for (int j = beg + lane; j < end; j += 32) {
        int s = csr[j];
        float e0 = asrc[s * 2] + ad0;     e0 = (e0 > 0.f) ? e0 : 0.2f * e0;
        float e1 = asrc[s * 2 + 1] + ad1; e1 = (e1 > 0.f) ? e1 : 0.2f * e1;
        m0 = fmaxf(m0, e0); m1 = fmaxf(m1, e1);
    }
    m0 = wredmax(m0); m1 = wredmax(m1);

    float d0 = 0.f, d1 = 0.f;
    for (int j = beg + lane; j < end; j += 32) {
        int s = csr[j];
        float e0 = asrc[s * 2] + ad0;     e0 = (e0 > 0.f) ? e0 : 0.2f * e0;
        float e1 = asrc[s * 2 + 1] + ad1; e1 = (e1 > 0.f) ? e1 : 0.2f * e1;
        d0 += expf(e0 - m0); d1 += expf(e1 - m1);
    }
    d0 = wredsum(d0); d1 = wredsum(d1);
    float inv0 = 1.0f / (d0 + 1e-16f), inv1 = 1.0f / (d1 + 1e-16f);

    float acc[8];
#pragma unroll
    for (int k = 0; k < 8; k++) acc[k] = 0.f;
    for (int j = beg; j < end; j++) {
        int s = csr[j];
        float e0 = asrc[s * 2] + ad0;     e0 = (e0 > 0.f) ? e0 : 0.2f * e0;
        float e1 = asrc[s * 2 + 1] + ad1; e1 = (e1 > 0.f) ? e1 : 0.2f * e1;
        float w0 = expf(e0 - m0) * inv0;
        float w1 = expf(e1 - m1) * inv1;
        const float* row = XH + (size_t)s * 256;
#pragma unroll
        for (int k = 0; k < 4; k++) {
            int c = lane + 32 * k;
            acc[k]     += row[c] * w0;
            acc[k + 4] += row[128 + c] * w1;
        }
    }
#pragma unroll
    for (int k = 0; k < 4; k++) {
        int c = lane + 32 * k;
        float v = 0.5f * (acc[k] + acc[k + 4]) + bias[c];
        v = (v > 0.f) ? v : 0.f;
        size_t off = (size_t)warp * 128 + c;
        Xout[off] = 0.5f * (XL[off] + XR[off]) + v;
    }
}

// ------------------------------ JK / final -----------------------------------
__global__ void k_jk(const float* __restrict__ XS, const float* __restrict__ SCF,
                     const float* __restrict__ SCB, float* __restrict__ JK, int n) {
    int idx = blockIdx.x * blockDim.x + threadIdx.x;
    if (idx >= n * 128) return;
    int node = idx >> 7;
    float s0 = SCF[node] + SCB[node];
    float s1 = SCF[n + node] + SCB[n + node];
    float s2 = SCF[2 * n + node] + SCB[2 * n + node];
    float m = fmaxf(s0, fmaxf(s1, s2));
    float e0 = expf(s0 - m), e1 = expf(s1 - m), e2 = expf(s2 - m);
    float inv = 1.0f / (e0 + e1 + e2);
    float v = e0 * XS[idx] + e1 * XS[(size_t)n * 128 + idx] + e2 * XS[(size_t)2 * n * 128 + idx];
    JK[idx] = v * inv;
}

__global__ void k_final(const float* __restrict__ OUTS, const float* __restrict__ lw,
                        float* __restrict__ out, int n) {
    int warp = (blockIdx.x * blockDim.x + threadIdx.x) >> 5;
    int lane = threadIdx.x & 31;
    if (warp >= n) return;
    float v[4][4];
    float s[4];
#pragma unroll
    for (int i = 0; i < 4; i++) {
        const float* row = OUTS + (size_t)i * n * 128 + (size_t)warp * 128;
        float p = 0.f;
#pragma unroll
        for (int k = 0; k < 4; k++) {
            int c = lane + 32 * k;
            v[i][k] = row[c];
            p += v[i][k] * lw[c];
        }
        s[i] = wredsum(p);
    }
    float m = fmaxf(fmaxf(s[0], s[1]), fmaxf(s[2], s[3]));
    float e[4];
    float den = 0.f;
#pragma unroll
    for (int i = 0; i < 4; i++) { e[i] = expf(s[i] - m); den += e[i]; }
    float inv = 1.0f / den;
#pragma unroll
    for (int k = 0; k < 4; k++) {
        int c = lane + 32 * k;
        float r = 0.f;
#pragma unroll
        for (int i = 0; i < 4; i++) r += v[i][k] * (e[i] * inv);
        out[(size_t)warp * 128 + c] = r;
    }
}

// ------------------------------ host ------------------------------------------
#define GETSYM(ptr, sym) do { void* _t = nullptr; cudaGetSymbolAddress(&_t, sym); \
                              ptr = (decltype(ptr))_t; } while (0)

static inline void launch_gemm(const float* A, const float* Bt, const float* bias,
                               float* C, int M, int N, int K) {
    dim3 grid(N / 128, (M + 127) / 128);
    gemm_mma<<<grid, 256, GEMM_SMEM>>>(A, Bt, bias, C, M, N, K);
}

extern "C" void kernel_launch(void* const* d_in, const int* in_sizes, int n_in,
                              void* d_out, int out_size) {
    const int*   x_idx    = (const int*)d_in[0];
    const float* x_flt    = (const float*)d_in[1];
    const int*   ei_l     = (const int*)d_in[2];
    const int*   ei_r     = (const int*)d_in[3];
    const float* emb_aa   = (const float*)d_in[4];
    const float* emb_ss   = (const float*)d_in[5];
    const float* conv_W   = (const float*)d_in[6];
    const float* att_src  = (const float*)d_in[7];
    const float* att_dst  = (const float*)d_in[8];
    const float* conv_b   = (const float*)d_in[9];
    const float* lstm_Wih = (const float*)d_in[10];
    const float* lstm_Whh = (const float*)d_in[11];
    const float* lstm_bih = (const float*)d_in[12];
    const float* lstm_bhh = (const float*)d_in[13];
    const float* jk_att_W = (const float*)d_in[14];
    /* d_in[15] jk_att_b: constant over L, cancels in softmax */
    const float* dummy_W  = (const float*)d_in[16];
    const float* dummy_b  = (const float*)d_in[17];
    const float* fin_W    = (const float*)d_in[18];
    const float* fin_b    = (const float*)d_in[19];
    const float* last_W   = (const float*)d_in[20];

    const int N = in_sizes[0] / 2;
    const int E = in_sizes[2] / 2;

    static bool attr_done = false;
    if (!attr_done) {
        cudaFuncSetAttribute(gemm_mma, cudaFuncAttributeMaxDynamicSharedMemorySize, GEMM_SMEM);
        cudaFuncSetAttribute(lstm_gemm, cudaFuncAttributeMaxDynamicSharedMemorySize, GEMM_SMEM);
        attr_done = true;
    }

    float *X0L, *X0R, *XSL, *XSR, *XH, *ASRC, *ADST, *HA, *HB, *CC;
    float *SCF, *SCB, *JKL, *JKR, *SQL, *SQR, *OUTS, *CWT, *DWT, *FWT;
    float *WIHP, *WHHP, *BSUMP;
    int *DEG, *PART, *IPL, *IPR, *CSL, *CSR2;
    GETSYM(X0L, g_X0L);  GETSYM(X0R, g_X0R);
    GETSYM(XSL, g_XSL);  GETSYM(XSR, g_XSR);
    GETSYM(XH, g_XH);
    GETSYM(ASRC, g_ASRC); GETSYM(ADST, g_ADST);
    GETSYM(HA, g_HA);    GETSYM(HB, g_HB);    GETSYM(CC, g_CC);
    GETSYM(SCF, g_SCF);  GETSYM(SCB, g_SCB);
    GETSYM(JKL, g_JKL);  GETSYM(JKR, g_JKR);
    GETSYM(SQL, g_SQL);  GETSYM(SQR, g_SQR);
    GETSYM(OUTS, g_OUTS);
    GETSYM(CWT, g_CWT);  GETSYM(DWT, g_DWT);  GETSYM(FWT, g_FWT);
    GETSYM(WIHP, g_WIHP); GETSYM(WHHP, g_WHHP); GETSYM(BSUMP, g_BSUMP);
    GETSYM(DEG, g_deg);  GETSYM(PART, g_part);
    GETSYM(IPL, g_indptrL); GETSYM(IPR, g_indptrR);
    GETSYM(CSL, g_csrL);    GETSYM(CSR2, g_csrR);

    const int TB = 256;
    const int NB = (N + 255) / 256;
    // ---- CSR per branch (edges invariant across layers) ----
    for (int b = 0; b < 2; b++) {
        const int* ei = b ? ei_r : ei_l;
        int* ip = b ? IPR : IPL;
        int* cs = b ? CSR2 : CSL;
        k_deg_init<<<(N + TB - 1) / TB, TB>>>(DEG, N);
        k_deg_count<<<(E + TB - 1) / TB, TB>>>(DEG, ei + E, E);
        k_scan1<<<NB, 256>>>(DEG, ip, PART, N);
        k_scan2<<<1, 512>>>(PART, NB);
        k_scan3<<<NB, 256>>>(ip, PART, N, NB);
        k_fill_self<<<(N + TB - 1) / TB, TB>>>(ip, cs, DEG, N);
        k_fill_edges<<<(E + TB - 1) / TB, TB>>>(ei, ei + E, DEG, cs, E);
    }

    // ---- weight prep ----
    k_transp<<<(6 * 128 * 256 + TB - 1) / TB, TB>>>(conv_W, CWT, 128, 256, 6 * 128 * 256);
    k_transp<<<(2 * 128 * 128 + TB - 1) / TB, TB>>>(dummy_W, DWT, 128, 128, 2 * 128 * 128);
    k_transp<<<(4 * 128 * 128 + TB - 1) / TB, TB>>>(fin_W, FWT, 128, 128, 4 * 128 * 128);
    k_permw<<<(4 * 768 * 128 + TB - 1) / TB, TB>>>(lstm_Wih, WIHP, 128, 4 * 768 * 128);
    k_permw<<<(4 * 768 * 192 + TB - 1) / TB, TB>>>(lstm_Whh, WHHP, 192, 4 * 768 * 192);
    k_bsump<<<(4 * 768 + TB - 1) / TB, TB>>>(lstm_bih, lstm_bhh, BSUMP, 4 * 768);

    // ---- input features ----
    k_init_x<<<(N * 128 + TB - 1) / TB, TB>>>(x_idx, x_flt, emb_aa, emb_ss, X0L, X0R, N);

    // ---- GAT layers ----
    const float* curL = X0L;
    const float* curR = X0R;
    for (int i = 0; i < 3; i++) {
        for (int b = 0; b < 2; b++) {
            const float* X = b ? curR : curL;
            float* Xnew = (b ? XSR : XSL) + (size_t)i * N * 128;
            int li = b * 3 + i;
            launch_gemm(X, CWT + (size_t)li * 256 * 128, nullptr, XH, N, 256, 128);
            k_att<<<(N * 32 + 127) / 128, 128>>>(XH, att_src + li * 256, att_dst + li * 256,
                                                 ASRC, ADST, N);
            k_gat_agg<<<(N * 32 + 127) / 128, 128>>>(XH, b ? IPR : IPL, b ? CSR2 : CSL,
                                                     ASRC, ADST, curL, curR,
                                                     conv_b + li * 128, Xnew, N);
        }
        curL = XSL + (size_t)i * N * 128;
        curR = XSR + (size_t)i * N * 128;
    }

    // ---- JK bi-LSTM per branch (fully fused timestep GEMMs) ----
    dim3 lgrid(6, (N + 127) / 128);
    for (int b = 0; b < 2; b++) {
        const float* XS = b ? XSR : XSL;
        k_zero<<<(3 * N + TB - 1) / TB, TB>>>(SCF, 3 * N);
        k_zero<<<(3 * N + TB - 1) / TB, TB>>>(SCB, 3 * N);
        for (int dir = 0; dir < 2; dir++) {
            int bd = b * 2 + dir;
            float* SC = dir ? SCB : SCF;
            const float* wseg = jk_att_W + b * 384 + dir * 192;
            const float* WI = WIHP + (size_t)bd * 768 * 128;
            const float* WH = WHHP + (size_t)bd * 768 * 192;
            const float* BS = BSUMP + (size_t)bd * 768;
            int t0 = dir ? 2 : 0, t2 = dir ? 0 : 2;
            lstm_gemm<<<lgrid, 256, GEMM_SMEM>>>(XS + (size_t)t0 * N * 128, WI, nullptr, WH,
                                                 BS, wseg, CC, HA, SC + (size_t)t0 * N, N, 0);
            lstm_gemm<<<lgrid, 256, GEMM_SMEM>>>(XS + (size_t)1 * N * 128, WI, HA, WH,
                                                 BS, wseg, CC, HB, SC + (size_t)1 * N, N, 6);
            lstm_gemm<<<lgrid, 256, GEMM_SMEM>>>(XS + (size_t)t2 * N * 128, WI, HB, WH,
                                                 BS, wseg, CC, HA, SC + (size_t)t2 * N, N, 6);
        }
        k_jk<<<(N * 128 + TB - 1) / TB, TB>>>(XS, SCF, SCB, b ? JKR : JKL, N);
    }

    // ---- heads ----
    launch_gemm(JKL, DWT,             dummy_b,       SQL, N, 128, 128);
    launch_gemm(JKR, DWT + 128 * 128, dummy_b + 128, SQR, N, 128, 128);
    {
        const float* feats[4] = {JKL, SQL, JKR, SQR};
        for (int i = 0; i < 4; i++) {
            launch_gemm(feats[i], FWT + (size_t)i * 128 * 128, fin_b + i * 128,
                        OUTS + (size_t)i * N * 128, N, 128, 128);
        }
    }
    k_final<<<(N * 32 + 127) / 128, 128>>>(OUTS, last_W, (float*)d_out, N);
}

// round 9
// speedup vs baseline: 3.9982x; 1.1841x over previous
#include <cuda_runtime.h>
#include <cuda_fp16.h>
#include <math.h>
#include <stdint.h>

#define NMAX 100000
#define EMAX 800000
#define ENMAX (NMAX + EMAX)

// ------------------------- static scratch (no allocs allowed) ----------------
__device__ float g_X0L[NMAX * 128];
__device__ float g_X0R[NMAX * 128];
__device__ float g_XSL[3 * NMAX * 128];
__device__ float g_XSR[3 * NMAX * 128];
__device__ __align__(16) __half g_hX0L[NMAX * 128];
__device__ __align__(16) __half g_hX0R[NMAX * 128];
__device__ __align__(16) __half g_hXSL[3 * NMAX * 128];
__device__ __align__(16) __half g_hXSR[3 * NMAX * 128];
__device__ float g_XH[NMAX * 256];
__device__ float g_ASRC[NMAX * 2];
__device__ float g_ADST[NMAX * 2];
__device__ __align__(16) __half g_HA[NMAX * 192];
__device__ __align__(16) __half g_HB[NMAX * 192];
__device__ float g_CC[NMAX * 192];
__device__ float g_SCF[3 * NMAX];
__device__ float g_SCB[3 * NMAX];
__device__ __align__(16) __half g_hJKL[NMAX * 128];
__device__ __align__(16) __half g_hJKR[NMAX * 128];
__device__ float g_OUTL[NMAX * 256];
__device__ float g_OUTR[NMAX * 256];
__device__ __align__(16) __half g_CWTh[6 * 256 * 128];   // conv_W^T fp16
__device__ __align__(16) __half g_WIHPh[4 * 768 * 128];  // Wih gate-interleaved fp16
__device__ __align__(16) __half g_WHHPh[4 * 768 * 192];  // Whh gate-interleaved fp16
__device__ float g_BSUMP[4 * 768];
__device__ __align__(16) __half g_BWL[256 * 128];        // folded head weights (L)
__device__ __align__(16) __half g_BWR[256 * 128];
__device__ float g_bbL[256];
__device__ float g_bbR[256];
__device__ int   g_deg[NMAX];
__device__ int   g_part[520];
__device__ int   g_indptrL[NMAX + 1];
__device__ int   g_indptrR[NMAX + 1];
__device__ int   g_csrL[ENMAX];
__device__ int   g_csrR[ENMAX];

// ------------------------------ helpers --------------------------------------
__device__ __forceinline__ float wredsum(float v) {
#pragma unroll
    for (int o = 16; o; o >>= 1) v += __shfl_xor_sync(0xffffffffu, v, o);
    return v;
}
__device__ __forceinline__ float wredmax(float v) {
#pragma unroll
    for (int o = 16; o; o >>= 1) v = fmaxf(v, __shfl_xor_sync(0xffffffffu, v, o));
    return v;
}
__device__ __forceinline__ float sigf(float x) { return 1.0f / (1.0f + expf(-x)); }

__device__ __forceinline__ void mma_f16(float* d, const uint32_t* a, const uint32_t* b) {
    asm volatile(
        "mma.sync.aligned.m16n8k16.row.col.f32.f16.f16.f32 "
        "{%0,%1,%2,%3}, {%4,%5,%6,%7}, {%8,%9}, {%0,%1,%2,%3};"
        : "+f"(d[0]), "+f"(d[1]), "+f"(d[2]), "+f"(d[3])
        : "r"(a[0]), "r"(a[1]), "r"(a[2]), "r"(a[3]), "r"(b[0]), "r"(b[1]));
}
__device__ __forceinline__ uint32_t su32(const void* p) {
    uint32_t a;
    asm("{ .reg .u64 t; cvta.to.shared.u64 t, %1; cvt.u32.u64 %0, t; }" : "=r"(a) : "l"(p));
    return a;
}
__device__ __forceinline__ void cpasync16(uint32_t dst, const void* src, int srcsize) {
    asm volatile("cp.async.ca.shared.global [%0], [%1], 16, %2;"
                 :: "r"(dst), "l"(src), "r"(srcsize));
}
__device__ __forceinline__ void cpacommit() { asm volatile("cp.async.commit_group;"); }
template <int n> __device__ __forceinline__ void cpawait() {
    asm volatile("cp.async.wait_group %0;" :: "n"(n));
}

// ------------------------------ CSR build ------------------------------------
__global__ void k_deg_init(int* deg, int n) {
    int i = blockIdx.x * blockDim.x + threadIdx.x;
    if (i < n) deg[i] = 1;  // self loop
}
__global__ void k_deg_count(int* deg, const int* dst, int e) {
    int i = blockIdx.x * blockDim.x + threadIdx.x;
    if (i < e) atomicAdd(&deg[dst[i]], 1);
}
__global__ void k_scan1(const int* __restrict__ in, int* __restrict__ out,
                        int* __restrict__ part, int n) {
    __shared__ int sh[256];
    int tid = threadIdx.x;
    int i = blockIdx.x * 256 + tid;
    int v = (i < n) ? in[i] : 0;
    sh[tid] = v;
    __syncthreads();
    for (int off = 1; off < 256; off <<= 1) {
        int t = (tid >= off) ? sh[tid - off] : 0;
        __syncthreads();
        sh[tid] += t;
        __syncthreads();
    }
    if (i < n) out[i] = sh[tid] - v;
    if (tid == 255) part[blockIdx.x] = sh[255];
}
__global__ void k_scan2(int* part, int nb) {
    __shared__ int sh[512];
    __shared__ int carry;
    int tid = threadIdx.x;
    if (tid == 0) carry = 0;
    __syncthreads();
    for (int base = 0; base < nb; base += 512) {
        int i = base + tid;
        int v = (i < nb) ? part[i] : 0;
        sh[tid] = v;
        __syncthreads();
        for (int off = 1; off < 512; off <<= 1) {
            int t = (tid >= off) ? sh[tid - off] : 0;
            __syncthreads();
            sh[tid] += t;
            __syncthreads();
        }
        if (i < nb) part[i] = carry + sh[tid] - v;
        int tot = sh[511];
        __syncthreads();
        if (tid == 0) carry += tot;
        __syncthreads();
    }
    if (tid == 0) part[nb] = carry;
}
__global__ void k_scan3(int* out, const int* part, int n, int nb) {
    int i = blockIdx.x * 256 + threadIdx.x;
    if (i < n) out[i] += part[i >> 8];
    if (i == 0) out[n] = part[nb];
}
__global__ void k_fill_self(const int* indptr, int* csr, int* pos, int n) {
    int i = blockIdx.x * blockDim.x + threadIdx.x;
    if (i < n) {
        int p = indptr[i];
        csr[p] = i;
        pos[i] = p + 1;
    }
}
__global__ void k_fill_edges(const int* src, const int* dst, int* pos, int* csr, int e) {
    int i = blockIdx.x * blockDim.x + threadIdx.x;
    if (i < e) {
        int p = atomicAdd(&pos[dst[i]], 1);
        csr[p] = src[i];
    }
}

// ------------------------------ features / prep ------------------------------
__global__ void k_init_x(const int* __restrict__ x_idx, const float* __restrict__ x_flt,
                         const float* __restrict__ eaa, const float* __restrict__ ess,
                         float* __restrict__ XL, float* __restrict__ XR,
                         __half* __restrict__ hXL, __half* __restrict__ hXR, int n) {
    int idx = blockIdx.x * blockDim.x + threadIdx.x;
    if (idx >= n * 128) return;
    int node = idx >> 7, c = idx & 127;
    float vl, vr;
    if (c < 123) {
        int i0 = x_idx[node * 2], i1 = x_idx[node * 2 + 1];
        vl = eaa[i0 * 123 + c] + ess[i1 * 123 + c];
        vr = eaa[26 * 123 + i0 * 123 + c] + ess[3 * 123 + i1 * 123 + c];
    } else {
        float f = x_flt[node * 5 + (c - 123)];
        vl = f; vr = f;
    }
    XL[idx] = vl;  XR[idx] = vr;
    hXL[idx] = __float2half_rn(vl);
    hXR[idx] = __float2half_rn(vr);
}
__global__ void k_zero(float* p, int total) {
    int i = blockIdx.x * blockDim.x + threadIdx.x;
    if (i < total) p[i] = 0.0f;
}
// W: [mats][K][N] -> WT(half): [mats][N][K]
__global__ void k_transp_h(const float* __restrict__ W, __half* __restrict__ WT,
                           int K, int N, int total) {
    int idx = blockIdx.x * blockDim.x + threadIdx.x;
    if (idx >= total) return;
    int per = K * N;
    int m = idx / per, rem = idx % per;
    int k = rem / N, n = rem % N;
    WT[(size_t)m * per + (size_t)n * K + k] = __float2half_rn(W[idx]);
}
// gate-interleave permute: out[bd][p][k] = in[bd][(p&3)*192 + (p>>2)][k]
__global__ void k_permw_h(const float* __restrict__ in, __half* __restrict__ out,
                          int K, int total) {
    int idx = blockIdx.x * blockDim.x + threadIdx.x;
    if (idx >= total) return;
    int per = 768 * K;
    int bd = idx / per, rem = idx % per;
    int p = rem / K, k = rem % K;
    int orig = (p & 3) * 192 + (p >> 2);
    out[idx] = __float2half_rn(in[(size_t)bd * per + (size_t)orig * K + k]);
}
__global__ void k_bsump(const float* bih, const float* bhh, float* out, int total) {
    int i = blockIdx.x * blockDim.x + threadIdx.x;
    if (i >= total) return;
    int bd = i / 768, p = i % 768;
    int orig = bd * 768 + (p & 3) * 192 + (p >> 2);
    out[i] = bih[orig] + bhh[orig];
}
// fold heads: BigW[n'][k]: n'<128 -> fin0^T; n'>=128 -> (dummy0 @ fin1)^T
__global__ void k_fold(const float* __restrict__ F0, const float* __restrict__ fb0,
                       const float* __restrict__ F1, const float* __restrict__ fb1,
                       const float* __restrict__ D0, const float* __restrict__ db0,
                       __half* __restrict__ BigW, float* __restrict__ bb) {
    int np = blockIdx.x, k = threadIdx.x;
    if (np < 128) {
        BigW[np * 128 + k] = __float2half_rn(F0[k * 128 + np]);
        if (k == 0) bb[np] = fb0[np];
    } else {
        int n = np - 128;
        float s = 0.f;
        for (int j = 0; j < 128; j++) s += D0[k * 128 + j] * F1[j * 128 + n];
        BigW[np * 128 + k] = __float2half_rn(s);
        if (k == 0) {
            float t = fb1[n];
            for (int j = 0; j < 128; j++) t += db0[j] * F1[j * 128 + n];
            bb[np] = t;
        }
    }
}

// ---------- pipelined fp16 tensor GEMM: C = A @ Bt^T (+bias) -----------------
// A [M,K] fp16 row-major, Bt [N,K] fp16 row-major. K%32==0, N%128==0.
__global__ void __launch_bounds__(256)
gemm_mma(const __half* __restrict__ A, const __half* __restrict__ Bt,
         const float* __restrict__ bias, float* __restrict__ C,
         int M, int N, int K) {
    __shared__ __align__(16) __half As[2][128][40];
    __shared__ __align__(16) __half Bs[2][128][40];
    const int tid = threadIdx.x;
    const int lane = tid & 31, wid = tid >> 5;
    const int wr = wid >> 2, wc = wid & 3;
    const int g = lane >> 2, q = lane & 3;
    const int bm = blockIdx.y * 128, bn = blockIdx.x * 128;

    float acc[4][4][4];
#pragma unroll
    for (int i = 0; i < 4; i++)
#pragma unroll
        for (int j = 0; j < 4; j++)
#pragma unroll
            for (int k = 0; k < 4; k++) acc[i][j][k] = 0.0f;

    const int nch = K >> 5;
#pragma unroll
    for (int i = 0; i < 2; i++) {
        int idx = tid + i * 256;
        int r = idx >> 2, c8 = (idx & 3) * 8;
        cpasync16(su32(&As[0][r][c8]), A + (size_t)(bm + r) * K + c8, (bm + r) < M ? 16 : 0);
        cpasync16(su32(&Bs[0][r][c8]), Bt + (size_t)(bn + r) * K + c8, 16);
    }
    cpacommit();

    for (int ch = 0; ch < nch; ch++) {
        const int buf = ch & 1;
        if (ch + 1 < nch) {
            int k0 = (ch + 1) * 32, nb = (ch + 1) & 1;
#pragma unroll
            for (int i = 0; i < 2; i++) {
                int idx = tid + i * 256;
                int r = idx >> 2, c8 = (idx & 3) * 8;
                cpasync16(su32(&As[nb][r][c8]), A + (size_t)(bm + r) * K + k0 + c8,
                          (bm + r) < M ? 16 : 0);
                cpasync16(su32(&Bs[nb][r][c8]), Bt + (size_t)(bn + r) * K + k0 + c8, 16);
            }
            cpacommit();
            cpawait<1>();
        } else {
            cpawait<0>();
        }
        __syncthreads();
#pragma unroll
        for (int ks = 0; ks < 2; ks++) {
            const int kk = ks * 16;
            uint32_t a[4][4], b[4][2];
#pragma unroll
            for (int mt = 0; mt < 4; mt++) {
                int r = wr * 64 + mt * 16 + g;
                a[mt][0] = *(const uint32_t*)&As[buf][r][kk + 2 * q];
                a[mt][1] = *(const uint32_t*)&As[buf][r + 8][kk + 2 * q];
                a[mt][2] = *(const uint32_t*)&As[buf][r][kk + 2 * q + 8];
                a[mt][3] = *(const uint32_t*)&As[buf][r + 8][kk + 2 * q + 8];
            }
#pragma unroll
            for (int nt = 0; nt < 4; nt++) {
                int c = wc * 32 + nt * 8 + g;
                b[nt][0] = *(const uint32_t*)&Bs[buf][c][kk + 2 * q];
                b[nt][1] = *(const uint32_t*)&Bs[buf][c][kk + 2 * q + 8];
            }
#pragma unroll
            for (int mt = 0; mt < 4; mt++)
#pragma unroll
                for (int nt = 0; nt < 4; nt++)
                    mma_f16(acc[mt][nt], a[mt], b[nt]);
        }
        __syncthreads();
    }

#pragma unroll
    for (int mt = 0; mt < 4; mt++) {
        int r0 = bm + wr * 64 + mt * 16 + g;
        int r1 = r0 + 8;
#pragma unroll
        for (int nt = 0; nt < 4; nt++) {
            int c0 = bn + wc * 32 + nt * 8 + 2 * q;
            float bx = 0.f, by = 0.f;
            if (bias) { bx = bias[c0]; by = bias[c0 + 1]; }
            if (r0 < M)
                *(float2*)(C + (size_t)r0 * N + c0) =
                    make_float2(acc[mt][nt][0] + bx, acc[mt][nt][1] + by);
            if (r1 < M)
                *(float2*)(C + (size_t)r1 * N + c0) =
                    make_float2(acc[mt][nt][2] + bx, acc[mt][nt][3] + by);
        }
    }
}

// ---------- fused LSTM timestep GEMM + cell + score (fp16 operands) ----------
__global__ void __launch_bounds__(256)
lstm_gemm(const __half* __restrict__ X, const __half* __restrict__ Wih,
          const __half* __restrict__ Hprev, const __half* __restrict__ Whh,
          const float* __restrict__ bsum, const float* __restrict__ wvec,
          float* __restrict__ Cmat, __half* __restrict__ Hout,
          float* __restrict__ SC, int M, int nch2) {
    __shared__ __align__(16) __half As[2][128][40];
    __shared__ __align__(16) __half Bs[2][128][40];
    const int tid = threadIdx.x;
    const int lane = tid & 31, wid = tid >> 5;
    const int wr = wid >> 2, wc = wid & 3;
    const int g = lane >> 2, q = lane & 3;
    const int bm = blockIdx.y * 128, bn = blockIdx.x * 128;

    float acc[4][4][4];
#pragma unroll
    for (int i = 0; i < 4; i++)
#pragma unroll
        for (int j = 0; j < 4; j++)
#pragma unroll
            for (int k = 0; k < 4; k++) acc[i][j][k] = 0.0f;

    const int nch = 4 + nch2;
#pragma unroll
    for (int i = 0; i < 2; i++) {
        int idx = tid + i * 256;
        int r = idx >> 2, c8 = (idx & 3) * 8;
        cpasync16(su32(&As[0][r][c8]), X + (size_t)(bm + r) * 128 + c8, (bm + r) < M ? 16 : 0);
        cpasync16(su32(&Bs[0][r][c8]), Wih + (size_t)(bn + r) * 128 + c8, 16);
    }
    cpacommit();

    for (int ch = 0; ch < nch; ch++) {
        const int buf = ch & 1;
        if (ch + 1 < nch) {
            int nc = ch + 1, nb = nc & 1;
            const __half* Asrc; const __half* Bsrc; int str, k0;
            if (nc < 4) { Asrc = X;     Bsrc = Wih; str = 128; k0 = nc * 32; }
            else        { Asrc = Hprev; Bsrc = Whh; str = 192; k0 = (nc - 4) * 32; }
#pragma unroll
            for (int i = 0; i < 2; i++) {
                int idx = tid + i * 256;
                int r = idx >> 2, c8 = (idx & 3) * 8;
                cpasync16(su32(&As[nb][r][c8]), Asrc + (size_t)(bm + r) * str + k0 + c8,
                          (bm + r) < M ? 16 : 0);
                cpasync16(su32(&Bs[nb][r][c8]), Bsrc + (size_t)(bn + r) * str + k0 + c8, 16);
            }
            cpacommit();
            cpawait<1>();
        } else {
            cpawait<0>();
        }
        __syncthreads();
#pragma unroll
        for (int ks = 0; ks < 2; ks++) {
            const int kk = ks * 16;
            uint32_t a[4][4], b[4][2];
#pragma unroll
            for (int mt = 0; mt < 4; mt++) {
                int r = wr * 64 + mt * 16 + g;
                a[mt][0] = *(const uint32_t*)&As[buf][r][kk + 2 * q];
                a[mt][1] = *(const uint32_t*)&As[buf][r + 8][kk + 2 * q];
                a[mt][2] = *(const uint32_t*)&As[buf][r][kk + 2 * q + 8];
                a[mt][3] = *(const uint32_t*)&As[buf][r + 8][kk + 2 * q + 8];
            }
#pragma unroll
            for (int nt = 0; nt < 4; nt++) {
                int c = wc * 32 + nt * 8 + g;
                b[nt][0] = *(const uint32_t*)&Bs[buf][c][kk + 2 * q];
                b[nt][1] = *(const uint32_t*)&Bs[buf][c][kk + 2 * q + 8];
            }
#pragma unroll
            for (int mt = 0; mt < 4; mt++)
#pragma unroll
                for (int nt = 0; nt < 4; nt++)
                    mma_f16(acc[mt][nt], a[mt], b[nt]);
        }
        __syncthreads();
    }

    // fused epilogue: lane pair (q, q^1) holds gates (i,f)/(g,o) of unit u
    const bool first = (nch2 == 0);
    float pr[4][2];
#pragma unroll
    for (int mt = 0; mt < 4; mt++) { pr[mt][0] = 0.f; pr[mt][1] = 0.f; }
#pragma unroll
    for (int nt = 0; nt < 4; nt++) {
        int c0 = bn + wc * 32 + nt * 8 + 2 * q;
        float b0 = bsum[c0], b1 = bsum[c0 + 1];
        int u = c0 >> 2;
        float wv = wvec[u];
#pragma unroll
        for (int mt = 0; mt < 4; mt++) {
            int r0 = bm + wr * 64 + mt * 16 + g, r1 = r0 + 8;
            float v0 = acc[mt][nt][0] + b0, v1 = acc[mt][nt][1] + b1;
            float w0 = acc[mt][nt][2] + b0, w1 = acc[mt][nt][3] + b1;
            float ov0 = __shfl_xor_sync(0xffffffffu, v0, 1);
            float ov1 = __shfl_xor_sync(0xffffffffu, v1, 1);
            float ow0 = __shfl_xor_sync(0xffffffffu, w0, 1);
            float ow1 = __shfl_xor_sync(0xffffffffu, w1, 1);
            if (!(q & 1)) {
                if (r0 < M) {
                    float cold = first ? 0.f : Cmat[(size_t)r0 * 192 + u];
                    float cn = sigf(v1) * cold + sigf(v0) * tanhf(ov0);
                    float h = sigf(ov1) * tanhf(cn);
                    Cmat[(size_t)r0 * 192 + u] = cn;
                    Hout[(size_t)r0 * 192 + u] = __float2half_rn(h);
                    pr[mt][0] += h * wv;
                }
                if (r1 < M) {
                    float cold = first ? 0.f : Cmat[(size_t)r1 * 192 + u];
                    float cn = sigf(w1) * cold + sigf(w0) * tanhf(ow0);
                    float h = sigf(ow1) * tanhf(cn);
                    Cmat[(size_t)r1 * 192 + u] = cn;
                    Hout[(size_t)r1 * 192 + u] = __float2half_rn(h);
                    pr[mt][1] += h * wv;
                }
            }
        }
    }
#pragma unroll
    for (int mt = 0; mt < 4; mt++) {
        float p0 = pr[mt][0] + __shfl_xor_sync(0xffffffffu, pr[mt][0], 2);
        float p1 = pr[mt][1] + __shfl_xor_sync(0xffffffffu, pr[mt][1], 2);
        if (q == 0) {
            int r0 = bm + wr * 64 + mt * 16 + g, r1 = r0 + 8;
            if (r0 < M) atomicAdd(SC + r0, p0);
            if (r1 < M) atomicAdd(SC + r1, p1);
        }
    }
}

// ------------------------------ GAT ------------------------------------------
__global__ void k_att(const float* __restrict__ XH, const float* __restrict__ ws,
                      const float* __restrict__ wd, float* __restrict__ asrc,
                      float* __restrict__ adst, int n) {
    int warp = (blockIdx.x * blockDim.x + threadIdx.x) >> 5;
    int lane = threadIdx.x & 31;
    if (warp >= n) return;
    const float* row = XH + (size_t)warp * 256;
    float s0 = 0, s1 = 0, d0 = 0, d1 = 0;
#pragma unroll
    for (int k = 0; k < 4; k++) {
        int c = lane + 32 * k;
        float x0 = row[c], x1 = row[128 + c];
        s0 += x0 * ws[c];  s1 += x1 * ws[128 + c];
        d0 += x0 * wd[c];  d1 += x1 * wd[128 + c];
    }
    s0 = wredsum(s0); s1 = wredsum(s1); d0 = wredsum(d0); d1 = wredsum(d1);
    if (lane == 0) {
        asrc[warp * 2] = s0; asrc[warp * 2 + 1] = s1;
        adst[warp * 2] = d0; adst[warp * 2 + 1] = d1;
    }
}

__global__ void k_gat_agg(const float* __restrict__ XH, const int* __restrict__ indptr,
                          const int* __restrict__ csr, const float* __restrict__ asrc,
                          const float* __restrict__ adst, const float* __restrict__ XL,
                          const float* __restrict__ XR, const float* __restrict__ bias,
                          float* __restrict__ Xout, __half* __restrict__ hXout, int n) {
    int warp = (blockIdx.x * blockDim.x + threadIdx.x) >> 5;
    int lane = threadIdx.x & 31;
    if (warp >= n) return;
    int beg = indptr[warp], end = indptr[warp + 1];
    float ad0 = adst[warp * 2], ad1 = adst[warp * 2 + 1];

    float m0 = -1e30f, m1 = -1e30f;
    for (int j = beg + lane; j < end; j += 32) {
        int s = csr[j];
        float e0 = asrc[s * 2] + ad0;     e0 = (e0 > 0.f) ? e0 : 0.2f * e0;
        float e1 = asrc[s * 2 + 1] + ad1; e1 = (e1 > 0.f) ? e1 : 0.2f * e1;
        m0 = fmaxf(m0, e0); m1 = fmaxf(m1, e1);
    }
    m0 = wredmax(m0); m1 = wredmax(m1);

    float d0 = 0.f, d1 = 0.f;
    for (int j = beg + lane; j < end; j += 32) {
        int s = csr[j];
        float e0 = asrc[s * 2] + ad0;     e0 = (e0 > 0.f) ? e0 : 0.2f * e0;
        float e1 = asrc[s * 2 + 1] + ad1; e1 = (e1 > 0.f) ? e1 : 0.2f * e1;
        d0 += expf(e0 - m0); d1 += expf(e1 - m1);
    }
    d0 = wredsum(d0); d1 = wredsum(d1);
    float inv0 = 1.0f / (d0 + 1e-16f), inv1 = 1.0f / (d1 + 1e-16f);

    float acc[8];
#pragma unroll
    for (int k = 0; k < 8; k++) acc[k] = 0.f;
    for (int j = beg; j < end; j++) {
        int s = csr[j];
        float e0 = asrc[s * 2] + ad0;     e0 = (e0 > 0.f) ? e0 : 0.2f * e0;
        float e1 = asrc[s * 2 + 1] + ad1; e1 = (e1 > 0.f) ? e1 : 0.2f * e1;
        float w0 = expf(e0 - m0) * inv0;
        float w1 = expf(e1 - m1) * inv1;
        const float* row = XH + (size_t)s * 256;
#pragma unroll
        for (int k = 0; k < 4; k++) {
            int c = lane + 32 * k;
            acc[k]     += row[c] * w0;
            acc[k + 4] += row[128 + c] * w1;
        }
    }
#pragma unroll
    for (int k = 0; k < 4; k++) {
        int c = lane + 32 * k;
        float v = 0.5f * (acc[k] + acc[k + 4]) + bias[c];
        v = (v > 0.f) ? v : 0.f;
        size_t off = (size_t)warp * 128 + c;
        float o = 0.5f * (XL[off] + XR[off]) + v;
        Xout[off] = o;
        hXout[off] = __float2half_rn(o);
    }
}

// ------------------------------ JK / final -----------------------------------
__global__ void k_jk(const float* __restrict__ XS, const float* __restrict__ SCF,
                     const float* __restrict__ SCB, __half* __restrict__ JK, int n) {
    int idx = blockIdx.x * blockDim.x + threadIdx.x;
    if (idx >= n * 128) return;
    int node = idx >> 7;
    float s0 = SCF[node] + SCB[node];
    float s1 = SCF[n + node] + SCB[n + node];
    float s2 = SCF[2 * n + node] + SCB[2 * n + node];
    float m = fmaxf(s0, fmaxf(s1, s2));
    float e0 = expf(s0 - m), e1 = expf(s1 - m), e2 = expf(s2 - m);
    float inv = 1.0f / (e0 + e1 + e2);
    float v = e0 * XS[idx] + e1 * XS[(size_t)n * 128 + idx] + e2 * XS[(size_t)2 * n * 128 + idx];
    JK[idx] = __float2half_rn(v * inv);
}

__global__ void k_final(const float* __restrict__ OUTL, const float* __restrict__ OUTR,
                        const float* __restrict__ lw, float* __restrict__ out, int n) {
    int warp = (blockIdx.x * blockDim.x + threadIdx.x) >> 5;
    int lane = threadIdx.x & 31;
    if (warp >= n) return;
    float v[4][4];
    float s[4];
#pragma unroll
    for (int i = 0; i < 4; i++) {
        const float* row = (i < 2 ? OUTL : OUTR) + (size_t)warp * 256 + (i & 1) * 128;
        float p = 0.f;
#pragma unroll
        for (int k = 0; k < 4; k++) {
            int c = lane + 32 * k;
            v[i][k] = row[c];
            p += v[i][k] * lw[c];
        }
        s[i] = wredsum(p);
    }
    float m = fmaxf(fmaxf(s[0], s[1]), fmaxf(s[2], s[3]));
    float e[4];
    float den = 0.f;
#pragma unroll
    for (int i = 0; i < 4; i++) { e[i] = expf(s[i] - m); den += e[i]; }
    float inv = 1.0f / den;
#pragma unroll
    for (int k = 0; k < 4; k++) {
        int c = lane + 32 * k;
        float r = 0.f;
#pragma unroll
        for (int i = 0; i < 4; i++) r += v[i][k] * (e[i] * inv);
        out[(size_t)warp * 128 + c] = r;
    }
}

// ------------------------------ host ------------------------------------------
#define GETSYM(ptr, sym) do { void* _t = nullptr; cudaGetSymbolAddress(&_t, sym); \
                              ptr = (decltype(ptr))_t; } while (0)

static inline void launch_gemm(const __half* A, const __half* Bt, const float* bias,
                               float* C, int M, int N, int K) {
    dim3 grid(N / 128, (M + 127) / 128);
    gemm_mma<<<grid, 256>>>(A, Bt, bias, C, M, N, K);
}

extern "C" void kernel_launch(void* const* d_in, const int* in_sizes, int n_in,
                              void* d_out, int out_size) {
    const int*   x_idx    = (const int*)d_in[0];
    const float* x_flt    = (const float*)d_in[1];
    const int*   ei_l     = (const int*)d_in[2];
    const int*   ei_r     = (const int*)d_in[3];
    const float* emb_aa   = (const float*)d_in[4];
    const float* emb_ss   = (const float*)d_in[5];
    const float* conv_W   = (const float*)d_in[6];
    const float* att_src  = (const float*)d_in[7];
    const float* att_dst  = (const float*)d_in[8];
    const float* conv_b   = (const float*)d_in[9];
    const float* lstm_Wih = (const float*)d_in[10];
    const float* lstm_Whh = (const float*)d_in[11];
    const float* lstm_bih = (const float*)d_in[12];
    const float* lstm_bhh = (const float*)d_in[13];
    const float* jk_att_W = (const float*)d_in[14];
    /* d_in[15] jk_att_b: constant over L, cancels in softmax */
    const float* dummy_W  = (const float*)d_in[16];
    const float* dummy_b  = (const float*)d_in[17];
    const float* fin_W    = (const float*)d_in[18];
    const float* fin_b    = (const float*)d_in[19];
    const float* last_W   = (const float*)d_in[20];

    const int N = in_sizes[0] / 2;
    const int E = in_sizes[2] / 2;

    float *X0L, *X0R, *XSL, *XSR, *XH, *ASRC, *ADST, *CC, *SCF, *SCB;
    float *OUTL, *OUTR, *BSUMP, *BBL, *BBR;
    __half *hX0L, *hX0R, *hXSL, *hXSR, *HA, *HB, *hJKL, *hJKR;
    __half *CWTh, *WIHPh, *WHHPh, *BWL, *BWR;
    int *DEG, *PART, *IPL, *IPR, *CSL, *CSR2;
    GETSYM(X0L, g_X0L);   GETSYM(X0R, g_X0R);
    GETSYM(XSL, g_XSL);   GETSYM(XSR, g_XSR);
    GETSYM(hX0L, g_hX0L); GETSYM(hX0R, g_hX0R);
    GETSYM(hXSL, g_hXSL); GETSYM(hXSR, g_hXSR);
    GETSYM(XH, g_XH);
    GETSYM(ASRC, g_ASRC); GETSYM(ADST, g_ADST);
    GETSYM(HA, g_HA);     GETSYM(HB, g_HB);     GETSYM(CC, g_CC);
    GETSYM(SCF, g_SCF);   GETSYM(SCB, g_SCB);
    GETSYM(hJKL, g_hJKL); GETSYM(hJKR, g_hJKR);
    GETSYM(OUTL, g_OUTL); GETSYM(OUTR, g_OUTR);
    GETSYM(CWTh, g_CWTh); GETSYM(WIHPh, g_WIHPh); GETSYM(WHHPh, g_WHHPh);
    GETSYM(BSUMP, g_BSUMP);
    GETSYM(BWL, g_BWL);   GETSYM(BWR, g_BWR);
    GETSYM(BBL, g_bbL);   GETSYM(BBR, g_bbR);
    GETSYM(DEG, g_deg);   GETSYM(PART, g_part);
    GETSYM(IPL, g_indptrL); GETSYM(IPR, g_indptrR);
    GETSYM(CSL, g_csrL);    GETSYM(CSR2, g_csrR);

    const int TB = 256;
    const int NB = (N + 255) / 256;
    // ---- CSR per branch ----
    for (int b = 0; b < 2; b++) {
        const int* ei = b ? ei_r : ei_l;
        int* ip = b ? IPR : IPL;
        int* cs = b ? CSR2 : CSL;
        k_deg_init<<<(N + TB - 1) / TB, TB>>>(DEG, N);
        k_deg_count<<<(E + TB - 1) / TB, TB>>>(DEG, ei + E, E);
        k_scan1<<<NB, 256>>>(DEG, ip, PART, N);
        k_scan2<<<1, 512>>>(PART, NB);
        k_scan3<<<NB, 256>>>(ip, PART, N, NB);
        k_fill_self<<<(N + TB - 1) / TB, TB>>>(ip, cs, DEG, N);
        k_fill_edges<<<(E + TB - 1) / TB, TB>>>(ei, ei + E, DEG, cs, E);
    }

    // ---- weight prep ----
    k_transp_h<<<(6 * 128 * 256 + TB - 1) / TB, TB>>>(conv_W, CWTh, 128, 256, 6 * 128 * 256);
    k_permw_h<<<(4 * 768 * 128 + TB - 1) / TB, TB>>>(lstm_Wih, WIHPh, 128, 4 * 768 * 128);
    k_permw_h<<<(4 * 768 * 192 + TB - 1) / TB, TB>>>(lstm_Whh, WHHPh, 192, 4 * 768 * 192);
    k_bsump<<<(4 * 768 + TB - 1) / TB, TB>>>(lstm_bih, lstm_bhh, BSUMP, 4 * 768);
    k_fold<<<256, 128>>>(fin_W, fin_b, fin_W + 16384, fin_b + 128,
                         dummy_W, dummy_b, BWL, BBL);
    k_fold<<<256, 128>>>(fin_W + 2 * 16384, fin_b + 256, fin_W + 3 * 16384, fin_b + 384,
                         dummy_W + 16384, dummy_b + 128, BWR, BBR);

    // ---- input features ----
    k_init_x<<<(N * 128 + TB - 1) / TB, TB>>>(x_idx, x_flt, emb_aa, emb_ss,
                                              X0L, X0R, hX0L, hX0R, N);

    // ---- GAT layers ----
    const float* curL = X0L;
    const float* curR = X0R;
    const __half* hcurL = hX0L;
    const __half* hcurR = hX0R;
    for (int i = 0; i < 3; i++) {
        for (int b = 0; b < 2; b++) {
            const __half* hX = b ? hcurR : hcurL;
            float* Xnew = (b ? XSR : XSL) + (size_t)i * N * 128;
            __half* hXnew = (b ? hXSR : hXSL) + (size_t)i * N * 128;
            int li = b * 3 + i;
            launch_gemm(hX, CWTh + (size_t)li * 256 * 128, nullptr, XH, N, 256, 128);
            k_att<<<(N * 32 + 127) / 128, 128>>>(XH, att_src + li * 256, att_dst + li * 256,
                                                 ASRC, ADST, N);
            k_gat_agg<<<(N * 32 + 127) / 128, 128>>>(XH, b ? IPR : IPL, b ? CSR2 : CSL,
                                                     ASRC, ADST, curL, curR,
                                                     conv_b + li * 128, Xnew, hXnew, N);
        }
        curL = XSL + (size_t)i * N * 128;
        curR = XSR + (size_t)i * N * 128;
        hcurL = hXSL + (size_t)i * N * 128;
        hcurR = hXSR + (size_t)i * N * 128;
    }

    // ---- JK bi-LSTM per branch (fused fp16 timestep GEMMs) ----
    dim3 lgrid(6, (N + 127) / 128);
    for (int b = 0; b < 2; b++) {
        const float* XS = b ? XSR : XSL;
        const __half* hXS = b ? hXSR : hXSL;
        k_zero<<<(3 * N + TB - 1) / TB, TB>>>(SCF, 3 * N);
        k_zero<<<(3 * N + TB - 1) / TB, TB>>>(SCB, 3 * N);
        for (int dir = 0; dir < 2; dir++) {
            int bd = b * 2 + dir;
            float* SC = dir ? SCB : SCF;
            const float* wseg = jk_att_W + b * 384 + dir * 192;
            const __half* WI = WIHPh + (size_t)bd * 768 * 128;
            const __half* WH = WHHPh + (size_t)bd * 768 * 192;
            const float* BS = BSUMP + (size_t)bd * 768;
            int t0 = dir ? 2 : 0, t2 = dir ? 0 : 2;
            lstm_gemm<<<lgrid, 256>>>(hXS + (size_t)t0 * N * 128, WI, nullptr, WH,
                                      BS, wseg, CC, HA, SC + (size_t)t0 * N, N, 0);
            lstm_gemm<<<lgrid, 256>>>(hXS + (size_t)1 * N * 128, WI, HA, WH,
                                      BS, wseg, CC, HB, SC + (size_t)1 * N, N, 6);
            lstm_gemm<<<lgrid, 256>>>(hXS + (size_t)t2 * N * 128, WI, HB, WH,
                                      BS, wseg, CC, HA, SC + (size_t)t2 * N, N, 6);
        }
        k_jk<<<(N * 128 + TB - 1) / TB, TB>>>(XS, SCF, SCB, b ? hJKR : hJKL, N);
    }

    // ---- heads (folded: one N=256 GEMM per branch) ----
    launch_gemm(hJKL, BWL, BBL, OUTL, N, 256, 128);
    launch_gemm(hJKR, BWR, BBR, OUTR, N, 256, 128);
    k_final<<<(N * 32 + 127) / 128, 128>>>(OUTL, OUTR, last_W, (float*)d_out, N);
}